// round 14
// baseline (speedup 1.0000x reference)
#include <cuda_runtime.h>
#include <cuda_fp16.h>
#include <math.h>

#define NN     50000
#define EE     800000
#define FIN    128
#define HID    32
#define HEADS  4
#define C1     128      // HEADS*HID
#define NCLS   16
#define NEG    0.2f
#define NEGINF_ORD 0x007FFFFFu   // f2o(-inf)

// ---------------- scratch (device globals; no allocation allowed) -----------
// NOTE: g_deg is zero on module load and re-zeroed by k_fincsr each call,
// so k_gemm1h's counting blocks can atomicAdd into it immediately.
__device__ __align__(16) __half   g_h1h [NN * C1];
__device__ __align__(16) float    g_als1[NN * HEADS];
__device__ __align__(16) float    g_ald1[NN * HEADS];
__device__ __align__(16) __half   g_h2h [NN * NCLS];
__device__ __align__(16) float    g_als2[NN];
__device__ __align__(16) float    g_ald2[NN];
__device__ __align__(16) unsigned g_maxu1[4];
__device__ __align__(16) unsigned g_maxu2[4];
__device__ __align__(16) int      g_deg   [NN];
__device__ __align__(16) int      g_rowloc[NN];      // block-local exclusive scan
__device__ __align__(16) int      g_rowfin[NN + 1];  // finalized rowptr
__device__ __align__(16) int      g_rank  [EE];
__device__ __align__(16) int      g_srcl  [EE];
__device__ __align__(16) __half   g_exlh  [EE * 4];  // per-slot fp16 exp weights
__device__ __align__(16) int      g_btot  [64];

// ---------------- helpers ----------------------------------------------------
__device__ __forceinline__ float lrelu(float v) { return v > 0.f ? v : NEG * v; }

__device__ __forceinline__ unsigned f2o(float f) {
    unsigned u = __float_as_uint(f);
    return (u & 0x80000000u) ? ~u : (u | 0x80000000u);
}
__device__ __forceinline__ float o2f(unsigned u) {
    return (u & 0x80000000u) ? __uint_as_float(u & 0x7fffffffu)
                             : __uint_as_float(~u);
}

__device__ __forceinline__ void ldm_x4(unsigned& r0, unsigned& r1, unsigned& r2, unsigned& r3,
                                       unsigned addr) {
    asm volatile("ldmatrix.sync.aligned.m8n8.x4.shared.b16 {%0,%1,%2,%3}, [%4];"
                 : "=r"(r0), "=r"(r1), "=r"(r2), "=r"(r3) : "r"(addr));
}
__device__ __forceinline__ void ldm_x4t(unsigned& r0, unsigned& r1, unsigned& r2, unsigned& r3,
                                        unsigned addr) {
    asm volatile("ldmatrix.sync.aligned.m8n8.x4.trans.shared.b16 {%0,%1,%2,%3}, [%4];"
                 : "=r"(r0), "=r"(r1), "=r"(r2), "=r"(r3) : "r"(addr));
}
__device__ __forceinline__ void mma16816(float* c, const unsigned* a, unsigned b0, unsigned b1) {
    asm volatile("mma.sync.aligned.m16n8k16.row.col.f32.f16.f16.f32 "
                 "{%0,%1,%2,%3}, {%4,%5,%6,%7}, {%8,%9}, {%0,%1,%2,%3};"
                 : "+f"(c[0]), "+f"(c[1]), "+f"(c[2]), "+f"(c[3])
                 : "r"(a[0]), "r"(a[1]), "r"(a[2]), "r"(a[3]), "r"(b0), "r"(b1));
}

// ---------------- GEMM1 via HMMA + overlapped degree counting ----------------
// blocks [0,391): GEMM tile (128 nodes).  blocks [391,1173): count+rank x4.
#define XSTR 136   // padded half stride for conflict-free ldmatrix
#define GB1  391
__global__ void __launch_bounds__(256, 2) k_gemm1h(const float* __restrict__ x,
                        const float* __restrict__ W1,
                        const float* __restrict__ a_src, const float* __restrict__ a_dst,
                        const int* __restrict__ ei) {
    const int tid  = threadIdx.x;

    if (blockIdx.x >= GB1) {
        // degree counting + per-edge rank (g_deg pre-zeroed)
        int e0 = ((blockIdx.x - GB1) * 256 + tid) * 4;
        if (e0 < EE) {
            int4 d4 = *(const int4*)(ei + EE + e0);
            int4 r4;
            r4.x = atomicAdd(&g_deg[d4.x], 1);
            r4.y = atomicAdd(&g_deg[d4.y], 1);
            r4.z = atomicAdd(&g_deg[d4.z], 1);
            r4.w = atomicAdd(&g_deg[d4.w], 1);
            *(int4*)(g_rank + e0) = r4;
        }
        return;
    }

    // per-call init of the max cells (consumed by later launches)
    if (blockIdx.x == 0) {
        if (tid < 4)  g_maxu1[tid] = NEGINF_ORD;
        if (tid == 4) g_maxu2[0] = NEGINF_ORD;
    }

    extern __shared__ __half dsm[];
    __half* xs = dsm;                 // [128][XSTR]
    __half* ws = dsm + 128 * XSTR;    // [128][XSTR]

    const int lane = tid & 31;
    const int warp = tid >> 5;
    const int nb   = blockIdx.x * 128;
    const int g    = lane >> 2;
    const int tig  = lane & 3;

    for (int i = tid; i < 128 * 32; i += 256) {
        int r = i >> 5, q = i & 31;
        float4 v = (nb + r < NN) ? *(const float4*)(x + (size_t)(nb + r) * 128 + q * 4)
                                 : make_float4(0.f, 0.f, 0.f, 0.f);
        __half2* dst = (__half2*)(xs + r * XSTR + q * 4);
        dst[0] = __floats2half2_rn(v.x, v.y);
        dst[1] = __floats2half2_rn(v.z, v.w);
    }
    for (int i = tid; i < 128 * 32; i += 256) {
        int r = i >> 5, q = i & 31;
        float4 v = *(const float4*)(W1 + r * 128 + q * 4);
        __half2* dst = (__half2*)(ws + r * XSTR + q * 4);
        dst[0] = __floats2half2_rn(v.x, v.y);
        dst[1] = __floats2half2_rn(v.z, v.w);
    }
    __syncthreads();

    unsigned xs_u = (unsigned)__cvta_generic_to_shared(xs);
    unsigned ws_u = (unsigned)__cvta_generic_to_shared(ws);
    unsigned aaddr = xs_u + ((warp * 16 + (lane & 15)) * XSTR + (lane >> 4) * 8) * 2;
    unsigned baddr = ws_u + ((lane & 15) * XSTR + (lane >> 4) * 8) * 2;

    float c[16][4];
#pragma unroll
    for (int j = 0; j < 16; j++)
#pragma unroll
        for (int q = 0; q < 4; q++) c[j][q] = 0.f;

#pragma unroll
    for (int ks = 0; ks < 8; ks++) {
        unsigned a[4];
        ldm_x4(a[0], a[1], a[2], a[3], aaddr + ks * 32);
#pragma unroll
        for (int p = 0; p < 8; p++) {
            unsigned b0, b1, b2, b3;
            ldm_x4t(b0, b1, b2, b3, baddr + ks * (16 * XSTR * 2) + p * 32);
            mma16816(c[2 * p],     a, b0, b1);
            mma16816(c[2 * p + 1], a, b2, b3);
        }
    }

    int r0 = nb + warp * 16 + g;
    int r1 = r0 + 8;
    bool v0 = r0 < NN, v1 = r1 < NN;
    float ss0[4] = {0, 0, 0, 0}, sd0[4] = {0, 0, 0, 0};
    float ss1[4] = {0, 0, 0, 0}, sd1[4] = {0, 0, 0, 0};
#pragma unroll
    for (int j = 0; j < 16; j++) {
        int col = j * 8 + tig * 2;
        float a0 = a_src[col], a1 = a_src[col + 1];
        float d0 = a_dst[col], d1 = a_dst[col + 1];
        int h = j >> 2;
        ss0[h] += c[j][0] * a0 + c[j][1] * a1;
        sd0[h] += c[j][0] * d0 + c[j][1] * d1;
        ss1[h] += c[j][2] * a0 + c[j][3] * a1;
        sd1[h] += c[j][2] * d0 + c[j][3] * d1;
        if (v0) *(__half2*)(g_h1h + (size_t)r0 * 128 + col) = __floats2half2_rn(c[j][0], c[j][1]);
        if (v1) *(__half2*)(g_h1h + (size_t)r1 * 128 + col) = __floats2half2_rn(c[j][2], c[j][3]);
    }
#pragma unroll
    for (int o = 1; o <= 2; o <<= 1) {
#pragma unroll
        for (int h = 0; h < 4; h++) {
            ss0[h] += __shfl_xor_sync(0xffffffffu, ss0[h], o);
            sd0[h] += __shfl_xor_sync(0xffffffffu, sd0[h], o);
            ss1[h] += __shfl_xor_sync(0xffffffffu, ss1[h], o);
            sd1[h] += __shfl_xor_sync(0xffffffffu, sd1[h], o);
        }
    }
    if (tig == 0) {
        if (v0) {
#pragma unroll
            for (int h = 0; h < 4; h++) {
                g_als1[r0 * 4 + h] = ss0[h];
                g_ald1[r0 * 4 + h] = sd0[h];
            }
        }
        if (v1) {
#pragma unroll
            for (int h = 0; h < 4; h++) {
                g_als1[r1 * 4 + h] = ss1[h];
                g_ald1[r1 * 4 + h] = sd1[h];
            }
        }
    }
}

// ---------------- scanA: per-1024 local scan + als1 max-reduce ---------------
// blocks [0,49): scan (writes g_rowloc).  blocks [49,54): max over als1.
__global__ void k_scanA() {
    if (blockIdx.x >= 49) {
        int t = (blockIdx.x - 49) * 1024 + threadIdx.x;   // 5120 threads
        float m0 = -1e30f, m1 = -1e30f, m2 = -1e30f, m3 = -1e30f;
        for (int n = t; n < NN; n += 5120) {
            float4 a = *(const float4*)(g_als1 + n * 4);
            m0 = fmaxf(m0, a.x); m1 = fmaxf(m1, a.y);
            m2 = fmaxf(m2, a.z); m3 = fmaxf(m3, a.w);
        }
#pragma unroll
        for (int o = 16; o >= 1; o >>= 1) {
            m0 = fmaxf(m0, __shfl_xor_sync(0xffffffffu, m0, o));
            m1 = fmaxf(m1, __shfl_xor_sync(0xffffffffu, m1, o));
            m2 = fmaxf(m2, __shfl_xor_sync(0xffffffffu, m2, o));
            m3 = fmaxf(m3, __shfl_xor_sync(0xffffffffu, m3, o));
        }
        if ((threadIdx.x & 31) == 0) {
            atomicMax(&g_maxu1[0], f2o(m0));
            atomicMax(&g_maxu1[1], f2o(m1));
            atomicMax(&g_maxu1[2], f2o(m2));
            atomicMax(&g_maxu1[3], f2o(m3));
        }
        return;
    }
    __shared__ int sw[32];
    int t = threadIdx.x, b = blockIdx.x;
    int i = b * 1024 + t;
    int v = (i < NN) ? g_deg[i] : 0;
    int x = v;
#pragma unroll
    for (int o = 1; o < 32; o <<= 1) {
        int y = __shfl_up_sync(0xffffffffu, x, o);
        if ((t & 31) >= o) x += y;
    }
    if ((t & 31) == 31) sw[t >> 5] = x;
    __syncthreads();
    if (t < 32) {
        int y = sw[t];
#pragma unroll
        for (int o = 1; o < 32; o <<= 1) {
            int z = __shfl_up_sync(0xffffffffu, y, o);
            if (t >= o) y += z;
        }
        sw[t] = y;
    }
    __syncthreads();
    int off = (t >= 32) ? sw[(t >> 5) - 1] : 0;
    int incl = x + off;
    if (i < NN) g_rowloc[i] = incl - v;     // block-local exclusive
    if (t == 1023) g_btot[b] = incl;
}

// ---------------- fincsr: finalize rowptr + scatter src & fp16 exp weights ---
// Each of 782 blocks: (1) redundantly scans the 49 block totals, (2) writes
// g_rowfin for its 64-node slice + re-zeros g_deg, (3) scatters 1024 edges:
// srcl[p] = s and g_exlh[p*4..p*4+3] = fp16 exp weights (one 8B store).
__global__ void __launch_bounds__(256) k_fincsr(const int* __restrict__ ei) {
    __shared__ int sh_boff[64];
    __shared__ int w0s;
    int t = threadIdx.x;
    int x = 0, v = 0;
    if (t < 64) {
        v = (t < 49) ? g_btot[t] : 0;
        x = v;
#pragma unroll
        for (int o = 1; o < 32; o <<= 1) {
            int y = __shfl_up_sync(0xffffffffu, x, o);
            if ((t & 31) >= o) x += y;
        }
        if (t == 31) w0s = x;
    }
    __syncthreads();
    if (t < 64) sh_boff[t] = (x + ((t >= 32) ? w0s : 0)) - v;
    __syncthreads();

    // finalize rowptr for this block's 64-node slice
    if (t < 64) {
        int i = blockIdx.x * 64 + t;
        if (i < NN) {
            g_rowfin[i] = g_rowloc[i] + sh_boff[i >> 10];
            g_deg[i] = 0;        // restore zeroed state for next call's count
        }
        if (i == NN) g_rowfin[NN] = EE;
    }

    // scatter 4 edges per thread: src id + fp16 exp weights
    int e0 = (blockIdx.x * 256 + t) * 4;
    if (e0 < EE) {
        int4 s4 = *(const int4*)(ei + e0);
        int4 d4 = *(const int4*)(ei + EE + e0);
        int4 r4 = *(const int4*)(g_rank + e0);
        uint4 mu = *(const uint4*)g_maxu1;
        float mx0 = o2f(mu.x), mx1 = o2f(mu.y), mx2 = o2f(mu.z), mx3 = o2f(mu.w);
        int ss[4] = {s4.x, s4.y, s4.z, s4.w};
        int dd[4] = {d4.x, d4.y, d4.z, d4.w};
        int rr[4] = {r4.x, r4.y, r4.z, r4.w};
        float4 as[4], ad[4];
        int p[4];
#pragma unroll
        for (int i = 0; i < 4; i++) {
            as[i] = *(const float4*)(g_als1 + (size_t)ss[i] * 4);
            ad[i] = *(const float4*)(g_ald1 + (size_t)dd[i] * 4);
            p[i]  = __ldg(&g_rowloc[dd[i]]) + sh_boff[dd[i] >> 10] + rr[i];
        }
#pragma unroll
        for (int i = 0; i < 4; i++) {
            float ex = __expf(lrelu(as[i].x + ad[i].x) - lrelu(mx0 + ad[i].x));
            float ey = __expf(lrelu(as[i].y + ad[i].y) - lrelu(mx1 + ad[i].y));
            float ez = __expf(lrelu(as[i].z + ad[i].z) - lrelu(mx2 + ad[i].z));
            float ew = __expf(lrelu(as[i].w + ad[i].w) - lrelu(mx3 + ad[i].w));
            __half2 e01 = __floats2half2_rn(ex, ey);
            __half2 e23 = __floats2half2_rn(ez, ew);
            g_srcl[p[i]] = ss[i];
            __half2* dst = (__half2*)(g_exlh + (size_t)p[i] * 4);
            dst[0] = e01;
            dst[1] = e23;
        }
    }
}

// ---------------- layer-1 aggregation + fused layer-2 projection -------------
// warp per dst node; shfl-broadcast src ids; fp16 exp weights loaded directly
// from g_exlh (L1-sequential LDG.U16); HFMA2 accumulation; then the SAME warp
// projects its act row through W2 (smem) -> h2h, als2/ald2, block max.
__global__ void __launch_bounds__(256) k_nodeagg1(const float* __restrict__ b1,
                        const float* __restrict__ W2, const float* __restrict__ a_src2,
                        const float* __restrict__ a_dst2) {
    __shared__ float w2s[2048];       // 8KB
    __shared__ float s_act[8][128];   // 4KB
    __shared__ float s_ps[8];
    const int tid = threadIdx.x;
    for (int i = tid; i < 2048; i += 256) w2s[i] = W2[i];
    __syncthreads();

    int wip  = tid >> 5;
    int gw   = (blockIdx.x * 256 + tid) >> 5;   // node id
    int lane = tid & 31;
    int sub  = lane >> 4;           // 2 edge slots
    int cl   = lane & 15;           // channel group: channels cl*8..cl*8+7
    int head = cl >> 2;
    bool denlane = (cl & 3) == 0;

    int start = g_rowfin[gw], end = g_rowfin[gw + 1];

    float den_l = 0.f;
    __half2 accA[4], accB[4];
    const __half2 hz = __floats2half2_rn(0.f, 0.f);
#pragma unroll
    for (int j = 0; j < 4; j++) { accA[j] = hz; accB[j] = hz; }

    // self loop (sub 0 only; exp computed here, once per node)
    {
        float ald_h = __ldg(g_ald1 + gw * 4 + head);
        float m_h = lrelu(o2f(g_maxu1[head]) + ald_h);
        float a_h = __ldg(g_als1 + gw * 4 + head);
        float ex = __expf(lrelu(a_h + ald_h) - m_h);
        if (sub == 0 && denlane) den_l = ex;
        if (sub == 0) {
            uint4 u = *(const uint4*)(g_h1h + (size_t)gw * 128 + cl * 8);
            const __half2* hp = (const __half2*)&u;
            __half2 eh = __float2half2_rn(ex);
#pragma unroll
            for (int q = 0; q < 4; q++) accA[q] = __hmul2(eh, hp[q]);
        }
    }

    for (int j0 = start; j0 < end; j0 += 32) {
        int idx = j0 + lane;
        int s = (idx < end) ? g_srcl[idx] : 0;
        int cnt = min(32, end - j0);
        for (int t = 0; t < cnt; t += 4) {
            int iA = t + sub, iB = t + 2 + sub;
            int sA = __shfl_sync(0xffffffffu, s, iA);
            int sB = __shfl_sync(0xffffffffu, s, iB);
            if (iA < cnt) {
                __half ehs = __ldg(g_exlh + (size_t)(j0 + iA) * 4 + head);
                uint4 uA = *(const uint4*)(g_h1h + (size_t)sA * 128 + cl * 8);
                if (denlane) den_l += __half2float(ehs);
                __half2 eh = __half2half2(ehs);
                const __half2* hA = (const __half2*)&uA;
#pragma unroll
                for (int q = 0; q < 4; q++) accA[q] = __hfma2(eh, hA[q], accA[q]);
            }
            if (iB < cnt) {
                __half ehs = __ldg(g_exlh + (size_t)(j0 + iB) * 4 + head);
                uint4 uB = *(const uint4*)(g_h1h + (size_t)sB * 128 + cl * 8);
                if (denlane) den_l += __half2float(ehs);
                __half2 eh = __half2half2(ehs);
                const __half2* hB = (const __half2*)&uB;
#pragma unroll
                for (int q = 0; q < 4; q++) accB[q] = __hfma2(eh, hB[q], accB[q]);
            }
        }
    }

    // to fp32, combine chains + subs
    float accF[8];
#pragma unroll
    for (int q = 0; q < 4; q++) {
        float2 fa = __half22float2(accA[q]);
        float2 fb = __half22float2(accB[q]);
        accF[q * 2]     = fa.x + fb.x;
        accF[q * 2 + 1] = fa.y + fb.y;
    }
#pragma unroll
    for (int j = 0; j < 8; j++) accF[j] += __shfl_xor_sync(0xffffffffu, accF[j], 16);
    den_l += __shfl_xor_sync(0xffffffffu, den_l, 16);
    float den = __shfl_sync(0xffffffffu, den_l, cl & 12, 16);

    // act row (ELU) -> smem for this warp's node
    if (sub == 0) {
        float inv = 1.f / den;
        float4 ba = ((const float4*)b1)[cl * 2];
        float4 bb = ((const float4*)b1)[cl * 2 + 1];
        float4 r0, r1;
        r0.x = accF[0] * inv + ba.x;  r0.x = r0.x > 0.f ? r0.x : expm1f(r0.x);
        r0.y = accF[1] * inv + ba.y;  r0.y = r0.y > 0.f ? r0.y : expm1f(r0.y);
        r0.z = accF[2] * inv + ba.z;  r0.z = r0.z > 0.f ? r0.z : expm1f(r0.z);
        r0.w = accF[3] * inv + ba.w;  r0.w = r0.w > 0.f ? r0.w : expm1f(r0.w);
        r1.x = accF[4] * inv + bb.x;  r1.x = r1.x > 0.f ? r1.x : expm1f(r1.x);
        r1.y = accF[5] * inv + bb.y;  r1.y = r1.y > 0.f ? r1.y : expm1f(r1.y);
        r1.z = accF[6] * inv + bb.z;  r1.z = r1.z > 0.f ? r1.z : expm1f(r1.z);
        r1.w = accF[7] * inv + bb.w;  r1.w = r1.w > 0.f ? r1.w : expm1f(r1.w);
        *(float4*)&s_act[wip][cl * 8]     = r0;
        *(float4*)&s_act[wip][cl * 8 + 4] = r1;
    }
    __syncwarp();

    // fused projection: h2[c] = sum_k act[k] * W2[k][c]
    int c = lane & 15, hh = lane >> 4;   // hh = k-half
    const float* ar = &s_act[wip][hh * 64];
    float acc2 = 0.f;
#pragma unroll 16
    for (int k = 0; k < 64; k++)
        acc2 = fmaf(ar[k], w2s[(hh * 64 + k) * 16 + c], acc2);
    acc2 += __shfl_xor_sync(0xffffffffu, acc2, 16);
    if (sub == 0) g_h2h[(size_t)gw * 16 + c] = __float2half_rn(acc2);
    float ps = acc2 * a_src2[c], pd = acc2 * a_dst2[c];
#pragma unroll
    for (int o = 8; o >= 1; o >>= 1) {
        ps += __shfl_xor_sync(0xffffffffu, ps, o, 16);
        pd += __shfl_xor_sync(0xffffffffu, pd, o, 16);
    }
    if (lane == 0) {
        g_als2[gw] = ps;
        g_ald2[gw] = pd;
        s_ps[wip] = ps;
    }
    __syncthreads();
    if (tid == 0) {
        float m = s_ps[0];
#pragma unroll
        for (int i = 1; i < 8; i++) m = fmaxf(m, s_ps[i]);
        atomicMax(&g_maxu2[0], f2o(m));
    }
}

// ---------------- layer-2 fused aggregation + log_softmax --------------------
// shfl-broadcast src ids; per-lane exp; 16 edges per inner iter (4 chains).
__global__ void __launch_bounds__(256) k_nodeagg2(const float* __restrict__ b2,
                                                  float* __restrict__ out) {
    int gw   = (blockIdx.x * 256 + threadIdx.x) >> 5;
    int lane = threadIdx.x & 31;
    int sub  = lane >> 3, cl = lane & 7;

    float ald = g_ald2[gw];
    float m = lrelu(o2f(g_maxu2[0]) + ald);
    int start = g_rowfin[gw], end = g_rowfin[gw + 1];

    float2 accA = make_float2(0.f, 0.f), accB = make_float2(0.f, 0.f);
    float2 accC = make_float2(0.f, 0.f), accD = make_float2(0.f, 0.f);
    float den_l = 0.f;

    // self loop
    {
        float exs = __expf(lrelu(__ldg(g_als2 + gw) + ald) - m);
        if (lane == 0) den_l = exs;
        if (sub == 0) {
            float2 f = __half22float2(*(const __half2*)(g_h2h + (size_t)gw * 16 + cl * 2));
            accA.x = exs * f.x;
            accA.y = exs * f.y;
        }
    }

    for (int j0 = start; j0 < end; j0 += 32) {
        int idx = j0 + lane;
        int s = (idx < end) ? g_srcl[idx] : 0;
        int cnt = min(32, end - j0);
        for (int t = 0; t < cnt; t += 16) {
            int iA = t + sub, iB = t + 4 + sub, iC = t + 8 + sub, iD = t + 12 + sub;
            int sA = __shfl_sync(0xffffffffu, s, iA);
            int sB = __shfl_sync(0xffffffffu, s, iB);
            int sC = __shfl_sync(0xffffffffu, s, iC);
            int sD = __shfl_sync(0xffffffffu, s, iD);
            if (iA < cnt) {
                float aA = __ldg(g_als2 + sA);
                float2 f = __half22float2(*(const __half2*)(g_h2h + (size_t)sA * 16 + cl * 2));
                float eA = __expf(lrelu(aA + ald) - m);
                if (cl == 0) den_l += eA;
                accA.x = fmaf(eA, f.x, accA.x);
                accA.y = fmaf(eA, f.y, accA.y);
            }
            if (iB < cnt) {
                float aB = __ldg(g_als2 + sB);
                float2 f = __half22float2(*(const __half2*)(g_h2h + (size_t)sB * 16 + cl * 2));
                float eB = __expf(lrelu(aB + ald) - m);
                if (cl == 0) den_l += eB;
                accB.x = fmaf(eB, f.x, accB.x);
                accB.y = fmaf(eB, f.y, accB.y);
            }
            if (iC < cnt) {
                float aC = __ldg(g_als2 + sC);
                float2 f = __half22float2(*(const __half2*)(g_h2h + (size_t)sC * 16 + cl * 2));
                float eC = __expf(lrelu(aC + ald) - m);
                if (cl == 0) den_l += eC;
                accC.x = fmaf(eC, f.x, accC.x);
                accC.y = fmaf(eC, f.y, accC.y);
            }
            if (iD < cnt) {
                float aD = __ldg(g_als2 + sD);
                float2 f = __half22float2(*(const __half2*)(g_h2h + (size_t)sD * 16 + cl * 2));
                float eD = __expf(lrelu(aD + ald) - m);
                if (cl == 0) den_l += eD;
                accD.x = fmaf(eD, f.x, accD.x);
                accD.y = fmaf(eD, f.y, accD.y);
            }
        }
    }
    accA.x += accB.x + accC.x + accD.x;
    accA.y += accB.y + accC.y + accD.y;
    accA.x += __shfl_xor_sync(0xffffffffu, accA.x, 8);
    accA.y += __shfl_xor_sync(0xffffffffu, accA.y, 8);
    accA.x += __shfl_xor_sync(0xffffffffu, accA.x, 16);
    accA.y += __shfl_xor_sync(0xffffffffu, accA.y, 16);
    den_l += __shfl_xor_sync(0xffffffffu, den_l, 8);
    den_l += __shfl_xor_sync(0xffffffffu, den_l, 16);
    float den = __shfl_sync(0xffffffffu, den_l, 0);

    float inv = 1.f / den;
    float v0 = accA.x * inv + b2[cl * 2];
    float v1 = accA.y * inv + b2[cl * 2 + 1];
    float mx = fmaxf(v0, v1);
#pragma unroll
    for (int o = 4; o >= 1; o >>= 1) mx = fmaxf(mx, __shfl_xor_sync(0xffffffffu, mx, o, 8));
    float s = __expf(v0 - mx) + __expf(v1 - mx);
#pragma unroll
    for (int o = 4; o >= 1; o >>= 1) s += __shfl_xor_sync(0xffffffffu, s, o, 8);
    if (sub == 0) {
        float ls = logf(s);
        float2 r = make_float2(v0 - mx - ls, v1 - mx - ls);
        *(float2*)(out + (size_t)gw * 16 + cl * 2) = r;
    }
}

// ---------------- launch ------------------------------------------------------
extern "C" void kernel_launch(void* const* d_in, const int* in_sizes, int n_in,
                              void* d_out, int out_size) {
    const float* x      = (const float*)d_in[0];
    const int*   ei     = (const int*)  d_in[1];
    const float* W1     = (const float*)d_in[2];
    const float* a_src1 = (const float*)d_in[3];
    const float* a_dst1 = (const float*)d_in[4];
    const float* b1     = (const float*)d_in[5];
    const float* W2     = (const float*)d_in[6];
    const float* a_src2 = (const float*)d_in[7];
    const float* a_dst2 = (const float*)d_in[8];
    const float* b2     = (const float*)d_in[9];
    float* out = (float*)d_out;

    const int smem1 = 2 * 128 * XSTR * sizeof(__half);   // 69632
    cudaFuncSetAttribute(k_gemm1h, cudaFuncAttributeMaxDynamicSharedMemorySize, smem1);

    k_gemm1h  <<<GB1 + 782, 256, smem1>>>(x, W1, a_src1, a_dst1, ei);
    k_scanA   <<<54, 1024>>>();
    k_fincsr  <<<782, 256>>>(ei);
    k_nodeagg1<<<6250, 256>>>(b1, W2, a_src2, a_dst2);
    k_nodeagg2<<<6250, 256>>>(b2, out);
}

// round 15
// speedup vs baseline: 1.0675x; 1.0675x over previous
#include <cuda_runtime.h>
#include <cuda_fp16.h>
#include <math.h>

#define NN     50000
#define EE     800000
#define FIN    128
#define HID    32
#define HEADS  4
#define C1     128      // HEADS*HID
#define NCLS   16
#define NEG    0.2f
#define NEGINF_ORD 0x007FFFFFu   // f2o(-inf)

// ---------------- scratch (device globals; no allocation allowed) -----------
// NOTE: g_deg is zero on module load and re-zeroed by k_fincsr each call,
// so k_gemm1h's counting blocks can atomicAdd into it immediately.
__device__ __align__(16) __half   g_h1h [NN * C1];
__device__ __align__(16) float    g_als1[NN * HEADS];
__device__ __align__(16) float    g_ald1[NN * HEADS];
__device__ __align__(16) __half   g_acth[NN * C1];   // fp16 layer-1 activations
__device__ __align__(16) __half   g_h2h [NN * NCLS];
__device__ __align__(16) float    g_als2[NN];
__device__ __align__(16) float    g_ald2[NN];
__device__ __align__(16) unsigned g_maxu1[4];
__device__ __align__(16) unsigned g_maxu2[4];
__device__ __align__(16) int      g_deg   [NN];
__device__ __align__(16) int      g_rowloc[NN];      // block-local exclusive scan
__device__ __align__(16) int      g_rowfin[NN + 1];  // finalized rowptr
__device__ __align__(16) int      g_rank  [EE];
__device__ __align__(16) int      g_srcl  [EE];
__device__ __align__(16) __half   g_exlh  [EE * 4];  // per-slot fp16 exp weights
__device__ __align__(16) int      g_btot  [64];

// ---------------- helpers ----------------------------------------------------
__device__ __forceinline__ float lrelu(float v) { return v > 0.f ? v : NEG * v; }

__device__ __forceinline__ unsigned f2o(float f) {
    unsigned u = __float_as_uint(f);
    return (u & 0x80000000u) ? ~u : (u | 0x80000000u);
}
__device__ __forceinline__ float o2f(unsigned u) {
    return (u & 0x80000000u) ? __uint_as_float(u & 0x7fffffffu)
                             : __uint_as_float(~u);
}

__device__ __forceinline__ void ldm_x4(unsigned& r0, unsigned& r1, unsigned& r2, unsigned& r3,
                                       unsigned addr) {
    asm volatile("ldmatrix.sync.aligned.m8n8.x4.shared.b16 {%0,%1,%2,%3}, [%4];"
                 : "=r"(r0), "=r"(r1), "=r"(r2), "=r"(r3) : "r"(addr));
}
__device__ __forceinline__ void ldm_x4t(unsigned& r0, unsigned& r1, unsigned& r2, unsigned& r3,
                                        unsigned addr) {
    asm volatile("ldmatrix.sync.aligned.m8n8.x4.trans.shared.b16 {%0,%1,%2,%3}, [%4];"
                 : "=r"(r0), "=r"(r1), "=r"(r2), "=r"(r3) : "r"(addr));
}
__device__ __forceinline__ void mma16816(float* c, const unsigned* a, unsigned b0, unsigned b1) {
    asm volatile("mma.sync.aligned.m16n8k16.row.col.f32.f16.f16.f32 "
                 "{%0,%1,%2,%3}, {%4,%5,%6,%7}, {%8,%9}, {%0,%1,%2,%3};"
                 : "+f"(c[0]), "+f"(c[1]), "+f"(c[2]), "+f"(c[3])
                 : "r"(a[0]), "r"(a[1]), "r"(a[2]), "r"(a[3]), "r"(b0), "r"(b1));
}

// ---------------- GEMM1 via HMMA + overlapped degree counting ----------------
// blocks [0,391): GEMM tile (128 nodes).  blocks [391,1173): count+rank x4.
#define XSTR 136   // padded half stride for conflict-free ldmatrix
#define GB1  391
__global__ void __launch_bounds__(256, 2) k_gemm1h(const float* __restrict__ x,
                        const float* __restrict__ W1,
                        const float* __restrict__ a_src, const float* __restrict__ a_dst,
                        const int* __restrict__ ei) {
    const int tid  = threadIdx.x;

    if (blockIdx.x >= GB1) {
        // degree counting + per-edge rank (g_deg pre-zeroed)
        int e0 = ((blockIdx.x - GB1) * 256 + tid) * 4;
        if (e0 < EE) {
            int4 d4 = *(const int4*)(ei + EE + e0);
            int4 r4;
            r4.x = atomicAdd(&g_deg[d4.x], 1);
            r4.y = atomicAdd(&g_deg[d4.y], 1);
            r4.z = atomicAdd(&g_deg[d4.z], 1);
            r4.w = atomicAdd(&g_deg[d4.w], 1);
            *(int4*)(g_rank + e0) = r4;
        }
        return;
    }

    // per-call init of the max cells (consumed by later launches)
    if (blockIdx.x == 0) {
        if (tid < 4)  g_maxu1[tid] = NEGINF_ORD;
        if (tid == 4) g_maxu2[0] = NEGINF_ORD;
    }

    extern __shared__ __half dsm[];
    __half* xs = dsm;                 // [128][XSTR]
    __half* ws = dsm + 128 * XSTR;    // [128][XSTR]

    const int lane = tid & 31;
    const int warp = tid >> 5;
    const int nb   = blockIdx.x * 128;
    const int g    = lane >> 2;
    const int tig  = lane & 3;

    for (int i = tid; i < 128 * 32; i += 256) {
        int r = i >> 5, q = i & 31;
        float4 v = (nb + r < NN) ? *(const float4*)(x + (size_t)(nb + r) * 128 + q * 4)
                                 : make_float4(0.f, 0.f, 0.f, 0.f);
        __half2* dst = (__half2*)(xs + r * XSTR + q * 4);
        dst[0] = __floats2half2_rn(v.x, v.y);
        dst[1] = __floats2half2_rn(v.z, v.w);
    }
    for (int i = tid; i < 128 * 32; i += 256) {
        int r = i >> 5, q = i & 31;
        float4 v = *(const float4*)(W1 + r * 128 + q * 4);
        __half2* dst = (__half2*)(ws + r * XSTR + q * 4);
        dst[0] = __floats2half2_rn(v.x, v.y);
        dst[1] = __floats2half2_rn(v.z, v.w);
    }
    __syncthreads();

    unsigned xs_u = (unsigned)__cvta_generic_to_shared(xs);
    unsigned ws_u = (unsigned)__cvta_generic_to_shared(ws);
    unsigned aaddr = xs_u + ((warp * 16 + (lane & 15)) * XSTR + (lane >> 4) * 8) * 2;
    unsigned baddr = ws_u + ((lane & 15) * XSTR + (lane >> 4) * 8) * 2;

    float c[16][4];
#pragma unroll
    for (int j = 0; j < 16; j++)
#pragma unroll
        for (int q = 0; q < 4; q++) c[j][q] = 0.f;

#pragma unroll
    for (int ks = 0; ks < 8; ks++) {
        unsigned a[4];
        ldm_x4(a[0], a[1], a[2], a[3], aaddr + ks * 32);
#pragma unroll
        for (int p = 0; p < 8; p++) {
            unsigned b0, b1, b2, b3;
            ldm_x4t(b0, b1, b2, b3, baddr + ks * (16 * XSTR * 2) + p * 32);
            mma16816(c[2 * p],     a, b0, b1);
            mma16816(c[2 * p + 1], a, b2, b3);
        }
    }

    int r0 = nb + warp * 16 + g;
    int r1 = r0 + 8;
    bool v0 = r0 < NN, v1 = r1 < NN;
    float ss0[4] = {0, 0, 0, 0}, sd0[4] = {0, 0, 0, 0};
    float ss1[4] = {0, 0, 0, 0}, sd1[4] = {0, 0, 0, 0};
#pragma unroll
    for (int j = 0; j < 16; j++) {
        int col = j * 8 + tig * 2;
        float a0 = a_src[col], a1 = a_src[col + 1];
        float d0 = a_dst[col], d1 = a_dst[col + 1];
        int h = j >> 2;
        ss0[h] += c[j][0] * a0 + c[j][1] * a1;
        sd0[h] += c[j][0] * d0 + c[j][1] * d1;
        ss1[h] += c[j][2] * a0 + c[j][3] * a1;
        sd1[h] += c[j][2] * d0 + c[j][3] * d1;
        if (v0) *(__half2*)(g_h1h + (size_t)r0 * 128 + col) = __floats2half2_rn(c[j][0], c[j][1]);
        if (v1) *(__half2*)(g_h1h + (size_t)r1 * 128 + col) = __floats2half2_rn(c[j][2], c[j][3]);
    }
#pragma unroll
    for (int o = 1; o <= 2; o <<= 1) {
#pragma unroll
        for (int h = 0; h < 4; h++) {
            ss0[h] += __shfl_xor_sync(0xffffffffu, ss0[h], o);
            sd0[h] += __shfl_xor_sync(0xffffffffu, sd0[h], o);
            ss1[h] += __shfl_xor_sync(0xffffffffu, ss1[h], o);
            sd1[h] += __shfl_xor_sync(0xffffffffu, sd1[h], o);
        }
    }
    if (tig == 0) {
        if (v0) {
#pragma unroll
            for (int h = 0; h < 4; h++) {
                g_als1[r0 * 4 + h] = ss0[h];
                g_ald1[r0 * 4 + h] = sd0[h];
            }
        }
        if (v1) {
#pragma unroll
            for (int h = 0; h < 4; h++) {
                g_als1[r1 * 4 + h] = ss1[h];
                g_ald1[r1 * 4 + h] = sd1[h];
            }
        }
    }
}

// ---------------- scanA: per-1024 local scan + als1 max-reduce ---------------
// blocks [0,49): scan (writes g_rowloc).  blocks [49,54): max over als1.
__global__ void k_scanA() {
    if (blockIdx.x >= 49) {
        int t = (blockIdx.x - 49) * 1024 + threadIdx.x;   // 5120 threads
        float m0 = -1e30f, m1 = -1e30f, m2 = -1e30f, m3 = -1e30f;
        for (int n = t; n < NN; n += 5120) {
            float4 a = *(const float4*)(g_als1 + n * 4);
            m0 = fmaxf(m0, a.x); m1 = fmaxf(m1, a.y);
            m2 = fmaxf(m2, a.z); m3 = fmaxf(m3, a.w);
        }
#pragma unroll
        for (int o = 16; o >= 1; o >>= 1) {
            m0 = fmaxf(m0, __shfl_xor_sync(0xffffffffu, m0, o));
            m1 = fmaxf(m1, __shfl_xor_sync(0xffffffffu, m1, o));
            m2 = fmaxf(m2, __shfl_xor_sync(0xffffffffu, m2, o));
            m3 = fmaxf(m3, __shfl_xor_sync(0xffffffffu, m3, o));
        }
        if ((threadIdx.x & 31) == 0) {
            atomicMax(&g_maxu1[0], f2o(m0));
            atomicMax(&g_maxu1[1], f2o(m1));
            atomicMax(&g_maxu1[2], f2o(m2));
            atomicMax(&g_maxu1[3], f2o(m3));
        }
        return;
    }
    __shared__ int sw[32];
    int t = threadIdx.x, b = blockIdx.x;
    int i = b * 1024 + t;
    int v = (i < NN) ? g_deg[i] : 0;
    int x = v;
#pragma unroll
    for (int o = 1; o < 32; o <<= 1) {
        int y = __shfl_up_sync(0xffffffffu, x, o);
        if ((t & 31) >= o) x += y;
    }
    if ((t & 31) == 31) sw[t >> 5] = x;
    __syncthreads();
    if (t < 32) {
        int y = sw[t];
#pragma unroll
        for (int o = 1; o < 32; o <<= 1) {
            int z = __shfl_up_sync(0xffffffffu, y, o);
            if (t >= o) y += z;
        }
        sw[t] = y;
    }
    __syncthreads();
    int off = (t >= 32) ? sw[(t >> 5) - 1] : 0;
    int incl = x + off;
    if (i < NN) g_rowloc[i] = incl - v;     // block-local exclusive
    if (t == 1023) g_btot[b] = incl;
}

// ---------------- fincsr: finalize rowptr + scatter src & fp16 exp weights ---
__global__ void __launch_bounds__(256) k_fincsr(const int* __restrict__ ei) {
    __shared__ int sh_boff[64];
    __shared__ int w0s;
    int t = threadIdx.x;
    int x = 0, v = 0;
    if (t < 64) {
        v = (t < 49) ? g_btot[t] : 0;
        x = v;
#pragma unroll
        for (int o = 1; o < 32; o <<= 1) {
            int y = __shfl_up_sync(0xffffffffu, x, o);
            if ((t & 31) >= o) x += y;
        }
        if (t == 31) w0s = x;
    }
    __syncthreads();
    if (t < 64) sh_boff[t] = (x + ((t >= 32) ? w0s : 0)) - v;
    __syncthreads();

    // finalize rowptr for this block's 64-node slice
    if (t < 64) {
        int i = blockIdx.x * 64 + t;
        if (i < NN) {
            g_rowfin[i] = g_rowloc[i] + sh_boff[i >> 10];
            g_deg[i] = 0;        // restore zeroed state for next call's count
        }
        if (i == NN) g_rowfin[NN] = EE;
    }

    // scatter 4 edges per thread: src id + fp16 exp weights
    int e0 = (blockIdx.x * 256 + t) * 4;
    if (e0 < EE) {
        int4 s4 = *(const int4*)(ei + e0);
        int4 d4 = *(const int4*)(ei + EE + e0);
        int4 r4 = *(const int4*)(g_rank + e0);
        uint4 mu = *(const uint4*)g_maxu1;
        float mx0 = o2f(mu.x), mx1 = o2f(mu.y), mx2 = o2f(mu.z), mx3 = o2f(mu.w);
        int ss[4] = {s4.x, s4.y, s4.z, s4.w};
        int dd[4] = {d4.x, d4.y, d4.z, d4.w};
        int rr[4] = {r4.x, r4.y, r4.z, r4.w};
        float4 as[4], ad[4];
        int p[4];
#pragma unroll
        for (int i = 0; i < 4; i++) {
            as[i] = *(const float4*)(g_als1 + (size_t)ss[i] * 4);
            ad[i] = *(const float4*)(g_ald1 + (size_t)dd[i] * 4);
            p[i]  = __ldg(&g_rowloc[dd[i]]) + sh_boff[dd[i] >> 10] + rr[i];
        }
#pragma unroll
        for (int i = 0; i < 4; i++) {
            float ex = __expf(lrelu(as[i].x + ad[i].x) - lrelu(mx0 + ad[i].x));
            float ey = __expf(lrelu(as[i].y + ad[i].y) - lrelu(mx1 + ad[i].y));
            float ez = __expf(lrelu(as[i].z + ad[i].z) - lrelu(mx2 + ad[i].z));
            float ew = __expf(lrelu(as[i].w + ad[i].w) - lrelu(mx3 + ad[i].w));
            __half2 e01 = __floats2half2_rn(ex, ey);
            __half2 e23 = __floats2half2_rn(ez, ew);
            g_srcl[p[i]] = ss[i];
            __half2* dst = (__half2*)(g_exlh + (size_t)p[i] * 4);
            dst[0] = e01;
            dst[1] = e23;
        }
    }
}

// ---------------- layer-1 aggregation (edge loop only) -----------------------
// warp per dst node; shfl-broadcast src ids; fp16 exp weights loaded directly
// from g_exlh; HFMA2 accumulation; epilogue = den divide + bias + ELU -> acth.
__global__ void __launch_bounds__(256) k_nodeagg1(const float* __restrict__ b1) {
    int gw   = (blockIdx.x * 256 + threadIdx.x) >> 5;   // node id
    int lane = threadIdx.x & 31;
    int sub  = lane >> 4;           // 2 edge slots
    int cl   = lane & 15;           // channel group: channels cl*8..cl*8+7
    int head = cl >> 2;
    bool denlane = (cl & 3) == 0;

    int start = g_rowfin[gw], end = g_rowfin[gw + 1];

    float den_l = 0.f;
    __half2 accA[4], accB[4];
    const __half2 hz = __floats2half2_rn(0.f, 0.f);
#pragma unroll
    for (int j = 0; j < 4; j++) { accA[j] = hz; accB[j] = hz; }

    // self loop (sub 0 only; exp computed here, once per node)
    {
        float ald_h = __ldg(g_ald1 + gw * 4 + head);
        float m_h = lrelu(o2f(g_maxu1[head]) + ald_h);
        float a_h = __ldg(g_als1 + gw * 4 + head);
        float ex = __expf(lrelu(a_h + ald_h) - m_h);
        if (sub == 0 && denlane) den_l = ex;
        if (sub == 0) {
            uint4 u = *(const uint4*)(g_h1h + (size_t)gw * 128 + cl * 8);
            const __half2* hp = (const __half2*)&u;
            __half2 eh = __float2half2_rn(ex);
#pragma unroll
            for (int q = 0; q < 4; q++) accA[q] = __hmul2(eh, hp[q]);
        }
    }

    for (int j0 = start; j0 < end; j0 += 32) {
        int idx = j0 + lane;
        int s = (idx < end) ? g_srcl[idx] : 0;
        int cnt = min(32, end - j0);
        for (int t = 0; t < cnt; t += 4) {
            int iA = t + sub, iB = t + 2 + sub;
            int sA = __shfl_sync(0xffffffffu, s, iA);
            int sB = __shfl_sync(0xffffffffu, s, iB);
            if (iA < cnt) {
                __half ehs = __ldg(g_exlh + (size_t)(j0 + iA) * 4 + head);
                uint4 uA = *(const uint4*)(g_h1h + (size_t)sA * 128 + cl * 8);
                if (denlane) den_l += __half2float(ehs);
                __half2 eh = __half2half2(ehs);
                const __half2* hA = (const __half2*)&uA;
#pragma unroll
                for (int q = 0; q < 4; q++) accA[q] = __hfma2(eh, hA[q], accA[q]);
            }
            if (iB < cnt) {
                __half ehs = __ldg(g_exlh + (size_t)(j0 + iB) * 4 + head);
                uint4 uB = *(const uint4*)(g_h1h + (size_t)sB * 128 + cl * 8);
                if (denlane) den_l += __half2float(ehs);
                __half2 eh = __half2half2(ehs);
                const __half2* hB = (const __half2*)&uB;
#pragma unroll
                for (int q = 0; q < 4; q++) accB[q] = __hfma2(eh, hB[q], accB[q]);
            }
        }
    }

    // to fp32, combine chains + subs
    float accF[8];
#pragma unroll
    for (int q = 0; q < 4; q++) {
        float2 fa = __half22float2(accA[q]);
        float2 fb = __half22float2(accB[q]);
        accF[q * 2]     = fa.x + fb.x;
        accF[q * 2 + 1] = fa.y + fb.y;
    }
#pragma unroll
    for (int j = 0; j < 8; j++) accF[j] += __shfl_xor_sync(0xffffffffu, accF[j], 16);
    den_l += __shfl_xor_sync(0xffffffffu, den_l, 16);
    float den = __shfl_sync(0xffffffffu, den_l, cl & 12, 16);

    // act row (ELU) -> g_acth fp16
    if (sub == 0) {
        float inv = 1.f / den;
        float4 ba = ((const float4*)b1)[cl * 2];
        float4 bb = ((const float4*)b1)[cl * 2 + 1];
        float4 r0, r1;
        r0.x = accF[0] * inv + ba.x;  r0.x = r0.x > 0.f ? r0.x : expm1f(r0.x);
        r0.y = accF[1] * inv + ba.y;  r0.y = r0.y > 0.f ? r0.y : expm1f(r0.y);
        r0.z = accF[2] * inv + ba.z;  r0.z = r0.z > 0.f ? r0.z : expm1f(r0.z);
        r0.w = accF[3] * inv + ba.w;  r0.w = r0.w > 0.f ? r0.w : expm1f(r0.w);
        r1.x = accF[4] * inv + bb.x;  r1.x = r1.x > 0.f ? r1.x : expm1f(r1.x);
        r1.y = accF[5] * inv + bb.y;  r1.y = r1.y > 0.f ? r1.y : expm1f(r1.y);
        r1.z = accF[6] * inv + bb.z;  r1.z = r1.z > 0.f ? r1.z : expm1f(r1.z);
        r1.w = accF[7] * inv + bb.w;  r1.w = r1.w > 0.f ? r1.w : expm1f(r1.w);
        uint4 st;
        ((__half2*)&st)[0] = __floats2half2_rn(r0.x, r0.y);
        ((__half2*)&st)[1] = __floats2half2_rn(r0.z, r0.w);
        ((__half2*)&st)[2] = __floats2half2_rn(r1.x, r1.y);
        ((__half2*)&st)[3] = __floats2half2_rn(r1.z, r1.w);
        *(uint4*)(g_acth + (size_t)gw * 128 + cl * 8) = st;
    }
}

// ---------------- GEMM2 via HMMA: h2h = fp16(acth @ W2) ; als2/ald2 + max ----
__global__ void __launch_bounds__(256, 2) k_gemm2h(const float* __restrict__ W2,
                        const float* __restrict__ a_src2, const float* __restrict__ a_dst2) {
    extern __shared__ __half dsm2[];
    __half* as_ = dsm2;                // [128][XSTR]
    __half* ws  = dsm2 + 128 * XSTR;   // [128][XSTR], only 16 cols used

    const int tid  = threadIdx.x;
    const int lane = tid & 31;
    const int warp = tid >> 5;
    const int nb   = blockIdx.x * 128;
    const int g    = lane >> 2;
    const int tig  = lane & 3;

    // stage A (acth rows, already fp16)
    for (int i = tid; i < 128 * 16; i += 256) {
        int r = i >> 4, q = i & 15;
        uint4 v = (nb + r < NN) ? *(const uint4*)(g_acth + (size_t)(nb + r) * 128 + q * 8)
                                : make_uint4(0u, 0u, 0u, 0u);
        *(uint4*)(as_ + r * XSTR + q * 8) = v;
    }
    // stage B (W2 128x16 float -> half)
    for (int i = tid; i < 1024; i += 256) {
        int r = i >> 3, q = i & 7;
        float2 v = *(const float2*)(W2 + r * 16 + q * 2);
        *(__half2*)(ws + r * XSTR + q * 2) = __floats2half2_rn(v.x, v.y);
    }
    __syncthreads();

    unsigned as_u = (unsigned)__cvta_generic_to_shared(as_);
    unsigned ws_u = (unsigned)__cvta_generic_to_shared(ws);
    unsigned aaddr = as_u + ((warp * 16 + (lane & 15)) * XSTR + (lane >> 4) * 8) * 2;
    unsigned baddr = ws_u + ((lane & 15) * XSTR + (lane >> 4) * 8) * 2;

    float c[2][4];
#pragma unroll
    for (int j = 0; j < 2; j++)
#pragma unroll
        for (int q = 0; q < 4; q++) c[j][q] = 0.f;

#pragma unroll
    for (int ks = 0; ks < 8; ks++) {
        unsigned a[4];
        ldm_x4(a[0], a[1], a[2], a[3], aaddr + ks * 32);
        unsigned b0, b1, b2, b3;
        ldm_x4t(b0, b1, b2, b3, baddr + ks * (16 * XSTR * 2));
        mma16816(c[0], a, b0, b1);
        mma16816(c[1], a, b2, b3);
    }

    int r0 = nb + warp * 16 + g;
    int r1 = r0 + 8;
    bool v0 = r0 < NN, v1 = r1 < NN;

    float ps0 = 0.f, pd0 = 0.f, ps1 = 0.f, pd1 = 0.f;
#pragma unroll
    for (int j = 0; j < 2; j++) {
        int col = j * 8 + tig * 2;
        float a0 = a_src2[col], a1 = a_src2[col + 1];
        float d0 = a_dst2[col], d1 = a_dst2[col + 1];
        ps0 += c[j][0] * a0 + c[j][1] * a1;
        pd0 += c[j][0] * d0 + c[j][1] * d1;
        ps1 += c[j][2] * a0 + c[j][3] * a1;
        pd1 += c[j][2] * d0 + c[j][3] * d1;
        if (v0) *(__half2*)(g_h2h + (size_t)r0 * 16 + col) = __floats2half2_rn(c[j][0], c[j][1]);
        if (v1) *(__half2*)(g_h2h + (size_t)r1 * 16 + col) = __floats2half2_rn(c[j][2], c[j][3]);
    }
#pragma unroll
    for (int o = 1; o <= 2; o <<= 1) {
        ps0 += __shfl_xor_sync(0xffffffffu, ps0, o);
        pd0 += __shfl_xor_sync(0xffffffffu, pd0, o);
        ps1 += __shfl_xor_sync(0xffffffffu, ps1, o);
        pd1 += __shfl_xor_sync(0xffffffffu, pd1, o);
    }
    float mx = -1e30f;
    if (tig == 0) {
        if (v0) { g_als2[r0] = ps0; g_ald2[r0] = pd0; mx = fmaxf(mx, ps0); }
        if (v1) { g_als2[r1] = ps1; g_ald2[r1] = pd1; mx = fmaxf(mx, ps1); }
    }
#pragma unroll
    for (int o = 16; o >= 1; o >>= 1) mx = fmaxf(mx, __shfl_xor_sync(0xffffffffu, mx, o));
    if (lane == 0) atomicMax(&g_maxu2[0], f2o(mx));
}

// ---------------- layer-2 fused aggregation + log_softmax --------------------
// shfl-broadcast src ids; per-lane exp; 16 edges per inner iter (4 chains).
__global__ void __launch_bounds__(256) k_nodeagg2(const float* __restrict__ b2,
                                                  float* __restrict__ out) {
    int gw   = (blockIdx.x * 256 + threadIdx.x) >> 5;
    int lane = threadIdx.x & 31;
    int sub  = lane >> 3, cl = lane & 7;

    float ald = g_ald2[gw];
    float m = lrelu(o2f(g_maxu2[0]) + ald);
    int start = g_rowfin[gw], end = g_rowfin[gw + 1];

    float2 accA = make_float2(0.f, 0.f), accB = make_float2(0.f, 0.f);
    float2 accC = make_float2(0.f, 0.f), accD = make_float2(0.f, 0.f);
    float den_l = 0.f;

    // self loop
    {
        float exs = __expf(lrelu(__ldg(g_als2 + gw) + ald) - m);
        if (lane == 0) den_l = exs;
        if (sub == 0) {
            float2 f = __half22float2(*(const __half2*)(g_h2h + (size_t)gw * 16 + cl * 2));
            accA.x = exs * f.x;
            accA.y = exs * f.y;
        }
    }

    for (int j0 = start; j0 < end; j0 += 32) {
        int idx = j0 + lane;
        int s = (idx < end) ? g_srcl[idx] : 0;
        int cnt = min(32, end - j0);
        for (int t = 0; t < cnt; t += 16) {
            int iA = t + sub, iB = t + 4 + sub, iC = t + 8 + sub, iD = t + 12 + sub;
            int sA = __shfl_sync(0xffffffffu, s, iA);
            int sB = __shfl_sync(0xffffffffu, s, iB);
            int sC = __shfl_sync(0xffffffffu, s, iC);
            int sD = __shfl_sync(0xffffffffu, s, iD);
            if (iA < cnt) {
                float aA = __ldg(g_als2 + sA);
                float2 f = __half22float2(*(const __half2*)(g_h2h + (size_t)sA * 16 + cl * 2));
                float eA = __expf(lrelu(aA + ald) - m);
                if (cl == 0) den_l += eA;
                accA.x = fmaf(eA, f.x, accA.x);
                accA.y = fmaf(eA, f.y, accA.y);
            }
            if (iB < cnt) {
                float aB = __ldg(g_als2 + sB);
                float2 f = __half22float2(*(const __half2*)(g_h2h + (size_t)sB * 16 + cl * 2));
                float eB = __expf(lrelu(aB + ald) - m);
                if (cl == 0) den_l += eB;
                accB.x = fmaf(eB, f.x, accB.x);
                accB.y = fmaf(eB, f.y, accB.y);
            }
            if (iC < cnt) {
                float aC = __ldg(g_als2 + sC);
                float2 f = __half22float2(*(const __half2*)(g_h2h + (size_t)sC * 16 + cl * 2));
                float eC = __expf(lrelu(aC + ald) - m);
                if (cl == 0) den_l += eC;
                accC.x = fmaf(eC, f.x, accC.x);
                accC.y = fmaf(eC, f.y, accC.y);
            }
            if (iD < cnt) {
                float aD = __ldg(g_als2 + sD);
                float2 f = __half22float2(*(const __half2*)(g_h2h + (size_t)sD * 16 + cl * 2));
                float eD = __expf(lrelu(aD + ald) - m);
                if (cl == 0) den_l += eD;
                accD.x = fmaf(eD, f.x, accD.x);
                accD.y = fmaf(eD, f.y, accD.y);
            }
        }
    }
    accA.x += accB.x + accC.x + accD.x;
    accA.y += accB.y + accC.y + accD.y;
    accA.x += __shfl_xor_sync(0xffffffffu, accA.x, 8);
    accA.y += __shfl_xor_sync(0xffffffffu, accA.y, 8);
    accA.x += __shfl_xor_sync(0xffffffffu, accA.x, 16);
    accA.y += __shfl_xor_sync(0xffffffffu, accA.y, 16);
    den_l += __shfl_xor_sync(0xffffffffu, den_l, 8);
    den_l += __shfl_xor_sync(0xffffffffu, den_l, 16);
    float den = __shfl_sync(0xffffffffu, den_l, 0);

    float inv = 1.f / den;
    float v0 = accA.x * inv + b2[cl * 2];
    float v1 = accA.y * inv + b2[cl * 2 + 1];
    float mx = fmaxf(v0, v1);
#pragma unroll
    for (int o = 4; o >= 1; o >>= 1) mx = fmaxf(mx, __shfl_xor_sync(0xffffffffu, mx, o, 8));
    float s = __expf(v0 - mx) + __expf(v1 - mx);
#pragma unroll
    for (int o = 4; o >= 1; o >>= 1) s += __shfl_xor_sync(0xffffffffu, s, o, 8);
    if (sub == 0) {
        float ls = logf(s);
        float2 r = make_float2(v0 - mx - ls, v1 - mx - ls);
        *(float2*)(out + (size_t)gw * 16 + cl * 2) = r;
    }
}

// ---------------- launch ------------------------------------------------------
extern "C" void kernel_launch(void* const* d_in, const int* in_sizes, int n_in,
                              void* d_out, int out_size) {
    const float* x      = (const float*)d_in[0];
    const int*   ei     = (const int*)  d_in[1];
    const float* W1     = (const float*)d_in[2];
    const float* a_src1 = (const float*)d_in[3];
    const float* a_dst1 = (const float*)d_in[4];
    const float* b1     = (const float*)d_in[5];
    const float* W2     = (const float*)d_in[6];
    const float* a_src2 = (const float*)d_in[7];
    const float* a_dst2 = (const float*)d_in[8];
    const float* b2     = (const float*)d_in[9];
    float* out = (float*)d_out;

    const int smem1 = 2 * 128 * XSTR * sizeof(__half);   // 69632
    cudaFuncSetAttribute(k_gemm1h, cudaFuncAttributeMaxDynamicSharedMemorySize, smem1);
    cudaFuncSetAttribute(k_gemm2h, cudaFuncAttributeMaxDynamicSharedMemorySize, smem1);

    k_gemm1h  <<<GB1 + 782, 256, smem1>>>(x, W1, a_src1, a_dst1, ei);
    k_scanA   <<<54, 1024>>>();
    k_fincsr  <<<782, 256>>>(ei);
    k_nodeagg1<<<6250, 256>>>(b1);
    k_gemm2h  <<<391, 256, smem1>>>(W2, a_src2, a_dst2);
    k_nodeagg2<<<6250, 256>>>(b2, out);
}

// round 16
// speedup vs baseline: 1.1633x; 1.0897x over previous
#include <cuda_runtime.h>
#include <cuda_fp16.h>
#include <math.h>

#define NN     50000
#define EE     800000
#define FIN    128
#define HID    32
#define HEADS  4
#define C1     128      // HEADS*HID
#define NCLS   16
#define NEG    0.2f
#define NEGINF_ORD 0x007FFFFFu   // f2o(-inf)

// ---------------- scratch (device globals; no allocation allowed) -----------
// NOTE: g_deg is zero on module load and re-zeroed by k_fincsr each call,
// so k_gemm1h's counting blocks can atomicAdd into it immediately.
__device__ __align__(16) __half   g_h1h [NN * C1];
__device__ __align__(16) float    g_als1[NN * HEADS];
__device__ __align__(16) float    g_ald1[NN * HEADS];
__device__ __align__(16) __half   g_acth[NN * C1];   // fp16 layer-1 activations
__device__ __align__(16) __half   g_h2h [NN * NCLS];
__device__ __align__(16) float    g_als2[NN];
__device__ __align__(16) float    g_ald2[NN];
__device__ __align__(16) unsigned g_maxu1[4];
__device__ __align__(16) unsigned g_maxu2[4];
__device__ __align__(16) int      g_deg   [NN];
__device__ __align__(16) int      g_rowloc[NN];      // block-local exclusive scan
__device__ __align__(16) int      g_rowfin[NN + 1];  // finalized rowptr
__device__ __align__(16) int      g_rank  [EE];
__device__ __align__(16) int      g_srcl  [EE];
__device__ __align__(16) __half   g_exlh  [EE * 4];  // per-slot fp16 exp weights
__device__ __align__(16) int      g_btot  [64];

// ---------------- helpers ----------------------------------------------------
__device__ __forceinline__ float lrelu(float v) { return v > 0.f ? v : NEG * v; }

__device__ __forceinline__ unsigned f2o(float f) {
    unsigned u = __float_as_uint(f);
    return (u & 0x80000000u) ? ~u : (u | 0x80000000u);
}
__device__ __forceinline__ float o2f(unsigned u) {
    return (u & 0x80000000u) ? __uint_as_float(u & 0x7fffffffu)
                             : __uint_as_float(~u);
}

__device__ __forceinline__ void ldm_x4(unsigned& r0, unsigned& r1, unsigned& r2, unsigned& r3,
                                       unsigned addr) {
    asm volatile("ldmatrix.sync.aligned.m8n8.x4.shared.b16 {%0,%1,%2,%3}, [%4];"
                 : "=r"(r0), "=r"(r1), "=r"(r2), "=r"(r3) : "r"(addr));
}
__device__ __forceinline__ void ldm_x4t(unsigned& r0, unsigned& r1, unsigned& r2, unsigned& r3,
                                        unsigned addr) {
    asm volatile("ldmatrix.sync.aligned.m8n8.x4.trans.shared.b16 {%0,%1,%2,%3}, [%4];"
                 : "=r"(r0), "=r"(r1), "=r"(r2), "=r"(r3) : "r"(addr));
}
__device__ __forceinline__ void mma16816(float* c, const unsigned* a, unsigned b0, unsigned b1) {
    asm volatile("mma.sync.aligned.m16n8k16.row.col.f32.f16.f16.f32 "
                 "{%0,%1,%2,%3}, {%4,%5,%6,%7}, {%8,%9}, {%0,%1,%2,%3};"
                 : "+f"(c[0]), "+f"(c[1]), "+f"(c[2]), "+f"(c[3])
                 : "r"(a[0]), "r"(a[1]), "r"(a[2]), "r"(a[3]), "r"(b0), "r"(b1));
}

// ---------------- GEMM1 via HMMA + overlapped degree counting ----------------
// blocks [0,391): GEMM tile (128 nodes).  blocks [391,1173): count+rank x4.
#define XSTR 136   // padded half stride for conflict-free ldmatrix
#define GB1  391
__global__ void __launch_bounds__(256, 2) k_gemm1h(const float* __restrict__ x,
                        const float* __restrict__ W1,
                        const float* __restrict__ a_src, const float* __restrict__ a_dst,
                        const int* __restrict__ ei) {
    const int tid  = threadIdx.x;

    if (blockIdx.x >= GB1) {
        // degree counting + per-edge rank (g_deg pre-zeroed)
        int e0 = ((blockIdx.x - GB1) * 256 + tid) * 4;
        if (e0 < EE) {
            int4 d4 = *(const int4*)(ei + EE + e0);
            int4 r4;
            r4.x = atomicAdd(&g_deg[d4.x], 1);
            r4.y = atomicAdd(&g_deg[d4.y], 1);
            r4.z = atomicAdd(&g_deg[d4.z], 1);
            r4.w = atomicAdd(&g_deg[d4.w], 1);
            *(int4*)(g_rank + e0) = r4;
        }
        return;
    }

    // per-call init of the max cells (consumed by later launches)
    if (blockIdx.x == 0) {
        if (tid < 4)  g_maxu1[tid] = NEGINF_ORD;
        if (tid == 4) g_maxu2[0] = NEGINF_ORD;
    }

    extern __shared__ __half dsm[];
    __half* xs = dsm;                 // [128][XSTR]
    __half* ws = dsm + 128 * XSTR;    // [128][XSTR]

    const int lane = tid & 31;
    const int warp = tid >> 5;
    const int nb   = blockIdx.x * 128;
    const int g    = lane >> 2;
    const int tig  = lane & 3;

    for (int i = tid; i < 128 * 32; i += 256) {
        int r = i >> 5, q = i & 31;
        float4 v = (nb + r < NN) ? *(const float4*)(x + (size_t)(nb + r) * 128 + q * 4)
                                 : make_float4(0.f, 0.f, 0.f, 0.f);
        __half2* dst = (__half2*)(xs + r * XSTR + q * 4);
        dst[0] = __floats2half2_rn(v.x, v.y);
        dst[1] = __floats2half2_rn(v.z, v.w);
    }
    for (int i = tid; i < 128 * 32; i += 256) {
        int r = i >> 5, q = i & 31;
        float4 v = *(const float4*)(W1 + r * 128 + q * 4);
        __half2* dst = (__half2*)(ws + r * XSTR + q * 4);
        dst[0] = __floats2half2_rn(v.x, v.y);
        dst[1] = __floats2half2_rn(v.z, v.w);
    }
    __syncthreads();

    unsigned xs_u = (unsigned)__cvta_generic_to_shared(xs);
    unsigned ws_u = (unsigned)__cvta_generic_to_shared(ws);
    unsigned aaddr = xs_u + ((warp * 16 + (lane & 15)) * XSTR + (lane >> 4) * 8) * 2;
    unsigned baddr = ws_u + ((lane & 15) * XSTR + (lane >> 4) * 8) * 2;

    float c[16][4];
#pragma unroll
    for (int j = 0; j < 16; j++)
#pragma unroll
        for (int q = 0; q < 4; q++) c[j][q] = 0.f;

#pragma unroll
    for (int ks = 0; ks < 8; ks++) {
        unsigned a[4];
        ldm_x4(a[0], a[1], a[2], a[3], aaddr + ks * 32);
#pragma unroll
        for (int p = 0; p < 8; p++) {
            unsigned b0, b1, b2, b3;
            ldm_x4t(b0, b1, b2, b3, baddr + ks * (16 * XSTR * 2) + p * 32);
            mma16816(c[2 * p],     a, b0, b1);
            mma16816(c[2 * p + 1], a, b2, b3);
        }
    }

    int r0 = nb + warp * 16 + g;
    int r1 = r0 + 8;
    bool v0 = r0 < NN, v1 = r1 < NN;
    float ss0[4] = {0, 0, 0, 0}, sd0[4] = {0, 0, 0, 0};
    float ss1[4] = {0, 0, 0, 0}, sd1[4] = {0, 0, 0, 0};
#pragma unroll
    for (int j = 0; j < 16; j++) {
        int col = j * 8 + tig * 2;
        float a0 = a_src[col], a1 = a_src[col + 1];
        float d0 = a_dst[col], d1 = a_dst[col + 1];
        int h = j >> 2;
        ss0[h] += c[j][0] * a0 + c[j][1] * a1;
        sd0[h] += c[j][0] * d0 + c[j][1] * d1;
        ss1[h] += c[j][2] * a0 + c[j][3] * a1;
        sd1[h] += c[j][2] * d0 + c[j][3] * d1;
        if (v0) *(__half2*)(g_h1h + (size_t)r0 * 128 + col) = __floats2half2_rn(c[j][0], c[j][1]);
        if (v1) *(__half2*)(g_h1h + (size_t)r1 * 128 + col) = __floats2half2_rn(c[j][2], c[j][3]);
    }
#pragma unroll
    for (int o = 1; o <= 2; o <<= 1) {
#pragma unroll
        for (int h = 0; h < 4; h++) {
            ss0[h] += __shfl_xor_sync(0xffffffffu, ss0[h], o);
            sd0[h] += __shfl_xor_sync(0xffffffffu, sd0[h], o);
            ss1[h] += __shfl_xor_sync(0xffffffffu, ss1[h], o);
            sd1[h] += __shfl_xor_sync(0xffffffffu, sd1[h], o);
        }
    }
    if (tig == 0) {
        if (v0) {
#pragma unroll
            for (int h = 0; h < 4; h++) {
                g_als1[r0 * 4 + h] = ss0[h];
                g_ald1[r0 * 4 + h] = sd0[h];
            }
        }
        if (v1) {
#pragma unroll
            for (int h = 0; h < 4; h++) {
                g_als1[r1 * 4 + h] = ss1[h];
                g_ald1[r1 * 4 + h] = sd1[h];
            }
        }
    }
}

// ---------------- scanA: per-1024 local scan + als1 max-reduce ---------------
// blocks [0,49): scan (writes g_rowloc).  blocks [49,54): max over als1.
__global__ void k_scanA() {
    if (blockIdx.x >= 49) {
        int t = (blockIdx.x - 49) * 1024 + threadIdx.x;   // 5120 threads
        float m0 = -1e30f, m1 = -1e30f, m2 = -1e30f, m3 = -1e30f;
        for (int n = t; n < NN; n += 5120) {
            float4 a = *(const float4*)(g_als1 + n * 4);
            m0 = fmaxf(m0, a.x); m1 = fmaxf(m1, a.y);
            m2 = fmaxf(m2, a.z); m3 = fmaxf(m3, a.w);
        }
#pragma unroll
        for (int o = 16; o >= 1; o >>= 1) {
            m0 = fmaxf(m0, __shfl_xor_sync(0xffffffffu, m0, o));
            m1 = fmaxf(m1, __shfl_xor_sync(0xffffffffu, m1, o));
            m2 = fmaxf(m2, __shfl_xor_sync(0xffffffffu, m2, o));
            m3 = fmaxf(m3, __shfl_xor_sync(0xffffffffu, m3, o));
        }
        if ((threadIdx.x & 31) == 0) {
            atomicMax(&g_maxu1[0], f2o(m0));
            atomicMax(&g_maxu1[1], f2o(m1));
            atomicMax(&g_maxu1[2], f2o(m2));
            atomicMax(&g_maxu1[3], f2o(m3));
        }
        return;
    }
    __shared__ int sw[32];
    int t = threadIdx.x, b = blockIdx.x;
    int i = b * 1024 + t;
    int v = (i < NN) ? g_deg[i] : 0;
    int x = v;
#pragma unroll
    for (int o = 1; o < 32; o <<= 1) {
        int y = __shfl_up_sync(0xffffffffu, x, o);
        if ((t & 31) >= o) x += y;
    }
    if ((t & 31) == 31) sw[t >> 5] = x;
    __syncthreads();
    if (t < 32) {
        int y = sw[t];
#pragma unroll
        for (int o = 1; o < 32; o <<= 1) {
            int z = __shfl_up_sync(0xffffffffu, y, o);
            if (t >= o) y += z;
        }
        sw[t] = y;
    }
    __syncthreads();
    int off = (t >= 32) ? sw[(t >> 5) - 1] : 0;
    int incl = x + off;
    if (i < NN) g_rowloc[i] = incl - v;     // block-local exclusive
    if (t == 1023) g_btot[b] = incl;
}

// ---------------- fincsr: finalize rowptr + scatter src & fp16 exp weights ---
__global__ void __launch_bounds__(256) k_fincsr(const int* __restrict__ ei) {
    __shared__ int sh_boff[64];
    __shared__ int w0s;
    int t = threadIdx.x;
    int x = 0, v = 0;
    if (t < 64) {
        v = (t < 49) ? g_btot[t] : 0;
        x = v;
#pragma unroll
        for (int o = 1; o < 32; o <<= 1) {
            int y = __shfl_up_sync(0xffffffffu, x, o);
            if ((t & 31) >= o) x += y;
        }
        if (t == 31) w0s = x;
    }
    __syncthreads();
    if (t < 64) sh_boff[t] = (x + ((t >= 32) ? w0s : 0)) - v;
    __syncthreads();

    // finalize rowptr for this block's 64-node slice
    if (t < 64) {
        int i = blockIdx.x * 64 + t;
        if (i < NN) {
            g_rowfin[i] = g_rowloc[i] + sh_boff[i >> 10];
            g_deg[i] = 0;        // restore zeroed state for next call's count
        }
        if (i == NN) g_rowfin[NN] = EE;
    }

    // scatter 4 edges per thread: src id + fp16 exp weights
    int e0 = (blockIdx.x * 256 + t) * 4;
    if (e0 < EE) {
        int4 s4 = *(const int4*)(ei + e0);
        int4 d4 = *(const int4*)(ei + EE + e0);
        int4 r4 = *(const int4*)(g_rank + e0);
        uint4 mu = *(const uint4*)g_maxu1;
        float mx0 = o2f(mu.x), mx1 = o2f(mu.y), mx2 = o2f(mu.z), mx3 = o2f(mu.w);
        int ss[4] = {s4.x, s4.y, s4.z, s4.w};
        int dd[4] = {d4.x, d4.y, d4.z, d4.w};
        int rr[4] = {r4.x, r4.y, r4.z, r4.w};
        float4 as[4], ad[4];
        int p[4];
#pragma unroll
        for (int i = 0; i < 4; i++) {
            as[i] = *(const float4*)(g_als1 + (size_t)ss[i] * 4);
            ad[i] = *(const float4*)(g_ald1 + (size_t)dd[i] * 4);
            p[i]  = __ldg(&g_rowloc[dd[i]]) + sh_boff[dd[i] >> 10] + rr[i];
        }
#pragma unroll
        for (int i = 0; i < 4; i++) {
            float ex = __expf(lrelu(as[i].x + ad[i].x) - lrelu(mx0 + ad[i].x));
            float ey = __expf(lrelu(as[i].y + ad[i].y) - lrelu(mx1 + ad[i].y));
            float ez = __expf(lrelu(as[i].z + ad[i].z) - lrelu(mx2 + ad[i].z));
            float ew = __expf(lrelu(as[i].w + ad[i].w) - lrelu(mx3 + ad[i].w));
            __half2 e01 = __floats2half2_rn(ex, ey);
            __half2 e23 = __floats2half2_rn(ez, ew);
            g_srcl[p[i]] = ss[i];
            __half2* dst = (__half2*)(g_exlh + (size_t)p[i] * 4);
            dst[0] = e01;
            dst[1] = e23;
        }
    }
}

// ---------------- layer-1 aggregation (edge loop only, branchless) -----------
// warp per dst node; shfl-broadcast src ids; predicated fp16 weight loads;
// unconditional h-row loads + HFMA2; epilogue = den divide + bias + ELU -> acth.
__global__ void __launch_bounds__(256) k_nodeagg1(const float* __restrict__ b1) {
    int gw   = (blockIdx.x * 256 + threadIdx.x) >> 5;   // node id
    int lane = threadIdx.x & 31;
    int sub  = lane >> 4;           // 2 edge slots
    int cl   = lane & 15;           // channel group: channels cl*8..cl*8+7
    int head = cl >> 2;
    bool denlane = (cl & 3) == 0;

    int start = g_rowfin[gw], end = g_rowfin[gw + 1];

    float den_l = 0.f;
    __half2 accA[4], accB[4];
    const __half2 hz = __floats2half2_rn(0.f, 0.f);
#pragma unroll
    for (int j = 0; j < 4; j++) { accA[j] = hz; accB[j] = hz; }

    // self loop (sub 0 only; exp computed here, once per node)
    {
        float ald_h = __ldg(g_ald1 + gw * 4 + head);
        float m_h = lrelu(o2f(g_maxu1[head]) + ald_h);
        float a_h = __ldg(g_als1 + gw * 4 + head);
        float ex = __expf(lrelu(a_h + ald_h) - m_h);
        if (sub == 0 && denlane) den_l = ex;
        if (sub == 0) {
            uint4 u = *(const uint4*)(g_h1h + (size_t)gw * 128 + cl * 8);
            const __half2* hp = (const __half2*)&u;
            __half2 eh = __float2half2_rn(ex);
#pragma unroll
            for (int q = 0; q < 4; q++) accA[q] = __hmul2(eh, hp[q]);
        }
    }

    const __half hzero = __ushort_as_half((unsigned short)0);
    for (int j0 = start; j0 < end; j0 += 32) {
        int idx = j0 + lane;
        int s = (idx < end) ? g_srcl[idx] : 0;
        int cnt = min(32, end - j0);
        for (int t = 0; t < cnt; t += 4) {
            int iA = t + sub, iB = t + 2 + sub;
            int sA = __shfl_sync(0xffffffffu, s, iA & 31);
            int sB = __shfl_sync(0xffffffffu, s, iB & 31);
            bool vA = iA < cnt, vB = iB < cnt;
            __half ehA = vA ? __ldg(g_exlh + (size_t)(j0 + iA) * 4 + head) : hzero;
            __half ehB = vB ? __ldg(g_exlh + (size_t)((j0 + iB) & (EE - 1 > 0 ? 0x7fffffff : 0)) * 4 + head) : hzero;
            uint4 uA = *(const uint4*)(g_h1h + (size_t)sA * 128 + cl * 8);
            uint4 uB = *(const uint4*)(g_h1h + (size_t)sB * 128 + cl * 8);
            den_l += denlane ? (__half2float(ehA) + __half2float(ehB)) : 0.f;
            __half2 e2A = __half2half2(ehA);
            __half2 e2B = __half2half2(ehB);
            const __half2* hA = (const __half2*)&uA;
            const __half2* hB = (const __half2*)&uB;
#pragma unroll
            for (int q = 0; q < 4; q++) {
                accA[q] = __hfma2(e2A, hA[q], accA[q]);
                accB[q] = __hfma2(e2B, hB[q], accB[q]);
            }
        }
    }

    // to fp32, combine chains + subs
    float accF[8];
#pragma unroll
    for (int q = 0; q < 4; q++) {
        float2 fa = __half22float2(accA[q]);
        float2 fb = __half22float2(accB[q]);
        accF[q * 2]     = fa.x + fb.x;
        accF[q * 2 + 1] = fa.y + fb.y;
    }
#pragma unroll
    for (int j = 0; j < 8; j++) accF[j] += __shfl_xor_sync(0xffffffffu, accF[j], 16);
    den_l += __shfl_xor_sync(0xffffffffu, den_l, 16);
    float den = __shfl_sync(0xffffffffu, den_l, cl & 12, 16);

    // act row (ELU via __expf) -> g_acth fp16
    if (sub == 0) {
        float inv = 1.f / den;
        float4 ba = ((const float4*)b1)[cl * 2];
        float4 bb = ((const float4*)b1)[cl * 2 + 1];
        float r[8];
        r[0] = accF[0] * inv + ba.x;
        r[1] = accF[1] * inv + ba.y;
        r[2] = accF[2] * inv + ba.z;
        r[3] = accF[3] * inv + ba.w;
        r[4] = accF[4] * inv + bb.x;
        r[5] = accF[5] * inv + bb.y;
        r[6] = accF[6] * inv + bb.z;
        r[7] = accF[7] * inv + bb.w;
#pragma unroll
        for (int q = 0; q < 8; q++) r[q] = r[q] > 0.f ? r[q] : (__expf(r[q]) - 1.f);
        uint4 st;
        ((__half2*)&st)[0] = __floats2half2_rn(r[0], r[1]);
        ((__half2*)&st)[1] = __floats2half2_rn(r[2], r[3]);
        ((__half2*)&st)[2] = __floats2half2_rn(r[4], r[5]);
        ((__half2*)&st)[3] = __floats2half2_rn(r[6], r[7]);
        *(uint4*)(g_acth + (size_t)gw * 128 + cl * 8) = st;
    }
}

// ---------------- GEMM2 via HMMA: h2h = fp16(acth @ W2) ; als2/ald2 + max ----
__global__ void __launch_bounds__(256, 2) k_gemm2h(const float* __restrict__ W2,
                        const float* __restrict__ a_src2, const float* __restrict__ a_dst2) {
    extern __shared__ __half dsm2[];
    __half* as_ = dsm2;                // [128][XSTR]
    __half* ws  = dsm2 + 128 * XSTR;   // [128][XSTR], only 16 cols used

    const int tid  = threadIdx.x;
    const int lane = tid & 31;
    const int warp = tid >> 5;
    const int nb   = blockIdx.x * 128;
    const int g    = lane >> 2;
    const int tig  = lane & 3;

    // stage A (acth rows, already fp16)
    for (int i = tid; i < 128 * 16; i += 256) {
        int r = i >> 4, q = i & 15;
        uint4 v = (nb + r < NN) ? *(const uint4*)(g_acth + (size_t)(nb + r) * 128 + q * 8)
                                : make_uint4(0u, 0u, 0u, 0u);
        *(uint4*)(as_ + r * XSTR + q * 8) = v;
    }
    // stage B (W2 128x16 float -> half)
    for (int i = tid; i < 1024; i += 256) {
        int r = i >> 3, q = i & 7;
        float2 v = *(const float2*)(W2 + r * 16 + q * 2);
        *(__half2*)(ws + r * XSTR + q * 2) = __floats2half2_rn(v.x, v.y);
    }
    __syncthreads();

    unsigned as_u = (unsigned)__cvta_generic_to_shared(as_);
    unsigned ws_u = (unsigned)__cvta_generic_to_shared(ws);
    unsigned aaddr = as_u + ((warp * 16 + (lane & 15)) * XSTR + (lane >> 4) * 8) * 2;
    unsigned baddr = ws_u + ((lane & 15) * XSTR + (lane >> 4) * 8) * 2;

    float c[2][4];
#pragma unroll
    for (int j = 0; j < 2; j++)
#pragma unroll
        for (int q = 0; q < 4; q++) c[j][q] = 0.f;

#pragma unroll
    for (int ks = 0; ks < 8; ks++) {
        unsigned a[4];
        ldm_x4(a[0], a[1], a[2], a[3], aaddr + ks * 32);
        unsigned b0, b1, b2, b3;
        ldm_x4t(b0, b1, b2, b3, baddr + ks * (16 * XSTR * 2));
        mma16816(c[0], a, b0, b1);
        mma16816(c[1], a, b2, b3);
    }

    int r0 = nb + warp * 16 + g;
    int r1 = r0 + 8;
    bool v0 = r0 < NN, v1 = r1 < NN;

    float ps0 = 0.f, pd0 = 0.f, ps1 = 0.f, pd1 = 0.f;
#pragma unroll
    for (int j = 0; j < 2; j++) {
        int col = j * 8 + tig * 2;
        float a0 = a_src2[col], a1 = a_src2[col + 1];
        float d0 = a_dst2[col], d1 = a_dst2[col + 1];
        ps0 += c[j][0] * a0 + c[j][1] * a1;
        pd0 += c[j][0] * d0 + c[j][1] * d1;
        ps1 += c[j][2] * a0 + c[j][3] * a1;
        pd1 += c[j][2] * d0 + c[j][3] * d1;
        if (v0) *(__half2*)(g_h2h + (size_t)r0 * 16 + col) = __floats2half2_rn(c[j][0], c[j][1]);
        if (v1) *(__half2*)(g_h2h + (size_t)r1 * 16 + col) = __floats2half2_rn(c[j][2], c[j][3]);
    }
#pragma unroll
    for (int o = 1; o <= 2; o <<= 1) {
        ps0 += __shfl_xor_sync(0xffffffffu, ps0, o);
        pd0 += __shfl_xor_sync(0xffffffffu, pd0, o);
        ps1 += __shfl_xor_sync(0xffffffffu, ps1, o);
        pd1 += __shfl_xor_sync(0xffffffffu, pd1, o);
    }
    float mx = -1e30f;
    if (tig == 0) {
        if (v0) { g_als2[r0] = ps0; g_ald2[r0] = pd0; mx = fmaxf(mx, ps0); }
        if (v1) { g_als2[r1] = ps1; g_ald2[r1] = pd1; mx = fmaxf(mx, ps1); }
    }
#pragma unroll
    for (int o = 16; o >= 1; o >>= 1) mx = fmaxf(mx, __shfl_xor_sync(0xffffffffu, mx, o));
    if (lane == 0) atomicMax(&g_maxu2[0], f2o(mx));
}

// ---------------- layer-2 fused aggregation + log_softmax (branchless) -------
__global__ void __launch_bounds__(256) k_nodeagg2(const float* __restrict__ b2,
                                                  float* __restrict__ out) {
    int gw   = (blockIdx.x * 256 + threadIdx.x) >> 5;
    int lane = threadIdx.x & 31;
    int sub  = lane >> 3, cl = lane & 7;

    float ald = g_ald2[gw];
    float m = lrelu(o2f(g_maxu2[0]) + ald);
    int start = g_rowfin[gw], end = g_rowfin[gw + 1];

    float2 accA = make_float2(0.f, 0.f), accB = make_float2(0.f, 0.f);
    float2 accC = make_float2(0.f, 0.f), accD = make_float2(0.f, 0.f);
    float den_l = 0.f;

    // self loop
    {
        float exs = __expf(lrelu(__ldg(g_als2 + gw) + ald) - m);
        if (lane == 0) den_l = exs;
        if (sub == 0) {
            float2 f = __half22float2(*(const __half2*)(g_h2h + (size_t)gw * 16 + cl * 2));
            accA.x = exs * f.x;
            accA.y = exs * f.y;
        }
    }

    for (int j0 = start; j0 < end; j0 += 32) {
        int idx = j0 + lane;
        int s = (idx < end) ? g_srcl[idx] : 0;
        int cnt = min(32, end - j0);
        for (int t = 0; t < cnt; t += 16) {
            int iA = t + sub, iB = t + 4 + sub, iC = t + 8 + sub, iD = t + 12 + sub;
            int sA = __shfl_sync(0xffffffffu, s, iA & 31);
            int sB = __shfl_sync(0xffffffffu, s, iB & 31);
            int sC = __shfl_sync(0xffffffffu, s, iC & 31);
            int sD = __shfl_sync(0xffffffffu, s, iD & 31);
            float aA = __ldg(g_als2 + sA);
            float aB = __ldg(g_als2 + sB);
            float aC = __ldg(g_als2 + sC);
            float aD = __ldg(g_als2 + sD);
            float2 fA = __half22float2(*(const __half2*)(g_h2h + (size_t)sA * 16 + cl * 2));
            float2 fB = __half22float2(*(const __half2*)(g_h2h + (size_t)sB * 16 + cl * 2));
            float2 fC = __half22float2(*(const __half2*)(g_h2h + (size_t)sC * 16 + cl * 2));
            float2 fD = __half22float2(*(const __half2*)(g_h2h + (size_t)sD * 16 + cl * 2));
            float eA = (iA < cnt) ? __expf(lrelu(aA + ald) - m) : 0.f;
            float eB = (iB < cnt) ? __expf(lrelu(aB + ald) - m) : 0.f;
            float eC = (iC < cnt) ? __expf(lrelu(aC + ald) - m) : 0.f;
            float eD = (iD < cnt) ? __expf(lrelu(aD + ald) - m) : 0.f;
            den_l += (cl == 0) ? (eA + eB + eC + eD) : 0.f;
            accA.x = fmaf(eA, fA.x, accA.x);  accA.y = fmaf(eA, fA.y, accA.y);
            accB.x = fmaf(eB, fB.x, accB.x);  accB.y = fmaf(eB, fB.y, accB.y);
            accC.x = fmaf(eC, fC.x, accC.x);  accC.y = fmaf(eC, fC.y, accC.y);
            accD.x = fmaf(eD, fD.x, accD.x);  accD.y = fmaf(eD, fD.y, accD.y);
        }
    }
    accA.x += accB.x + accC.x + accD.x;
    accA.y += accB.y + accC.y + accD.y;
    accA.x += __shfl_xor_sync(0xffffffffu, accA.x, 8);
    accA.y += __shfl_xor_sync(0xffffffffu, accA.y, 8);
    accA.x += __shfl_xor_sync(0xffffffffu, accA.x, 16);
    accA.y += __shfl_xor_sync(0xffffffffu, accA.y, 16);
    den_l += __shfl_xor_sync(0xffffffffu, den_l, 8);
    den_l += __shfl_xor_sync(0xffffffffu, den_l, 16);
    float den = __shfl_sync(0xffffffffu, den_l, 0);

    float inv = 1.f / den;
    float v0 = accA.x * inv + b2[cl * 2];
    float v1 = accA.y * inv + b2[cl * 2 + 1];
    float mx = fmaxf(v0, v1);
#pragma unroll
    for (int o = 4; o >= 1; o >>= 1) mx = fmaxf(mx, __shfl_xor_sync(0xffffffffu, mx, o, 8));
    float s = __expf(v0 - mx) + __expf(v1 - mx);
#pragma unroll
    for (int o = 4; o >= 1; o >>= 1) s += __shfl_xor_sync(0xffffffffu, s, o, 8);
    if (sub == 0) {
        float ls = __logf(s);
        float2 r = make_float2(v0 - mx - ls, v1 - mx - ls);
        *(float2*)(out + (size_t)gw * 16 + cl * 2) = r;
    }
}

// ---------------- launch ------------------------------------------------------
extern "C" void kernel_launch(void* const* d_in, const int* in_sizes, int n_in,
                              void* d_out, int out_size) {
    const float* x      = (const float*)d_in[0];
    const int*   ei     = (const int*)  d_in[1];
    const float* W1     = (const float*)d_in[2];
    const float* a_src1 = (const float*)d_in[3];
    const float* a_dst1 = (const float*)d_in[4];
    const float* b1     = (const float*)d_in[5];
    const float* W2     = (const float*)d_in[6];
    const float* a_src2 = (const float*)d_in[7];
    const float* a_dst2 = (const float*)d_in[8];
    const float* b2     = (const float*)d_in[9];
    float* out = (float*)d_out;

    const int smem1 = 2 * 128 * XSTR * sizeof(__half);   // 69632
    cudaFuncSetAttribute(k_gemm1h, cudaFuncAttributeMaxDynamicSharedMemorySize, smem1);
    cudaFuncSetAttribute(k_gemm2h, cudaFuncAttributeMaxDynamicSharedMemorySize, smem1);

    k_gemm1h  <<<GB1 + 782, 256, smem1>>>(x, W1, a_src1, a_dst1, ei);
    k_scanA   <<<54, 1024>>>();
    k_fincsr  <<<782, 256>>>(ei);
    k_nodeagg1<<<6250, 256>>>(b1);
    k_gemm2h  <<<391, 256, smem1>>>(W2, a_src2, a_dst2);
    k_nodeagg2<<<6250, 256>>>(b2, out);
}

// round 17
// speedup vs baseline: 1.1707x; 1.0064x over previous
#include <cuda_runtime.h>
#include <cuda_fp16.h>
#include <math.h>

#define NN     50000
#define EE     800000
#define FIN    128
#define HID    32
#define HEADS  4
#define C1     128      // HEADS*HID
#define NCLS   16
#define NEG    0.2f
#define NEGINF_ORD 0x007FFFFFu   // f2o(-inf)

// ---------------- scratch (device globals; no allocation allowed) -----------
// NOTE: g_deg is zero on module load and re-zeroed by k_fincsr each call,
// so k_gemm1h's counting blocks can atomicAdd into it immediately.
__device__ __align__(16) __half   g_h1h [NN * C1];
__device__ __align__(16) float    g_als1[NN * HEADS];
__device__ __align__(16) float    g_ald1[NN * HEADS];
__device__ __align__(16) __half   g_acth[NN * C1];   // fp16 layer-1 activations
__device__ __align__(16) __half   g_h2h [NN * NCLS];
__device__ __align__(16) float    g_als2[NN];
__device__ __align__(16) float    g_ald2[NN];
__device__ __align__(16) unsigned g_maxu1[4];
__device__ __align__(16) unsigned g_maxu2[4];
__device__ __align__(16) int      g_deg   [NN];
__device__ __align__(16) int      g_rowloc[NN];      // block-local exclusive scan
__device__ __align__(16) int      g_rowfin[NN + 1];  // finalized rowptr
__device__ __align__(16) int      g_rank  [EE];
__device__ __align__(16) int      g_srcl  [EE];
__device__ __align__(16) __half   g_exlh  [EE * 4];  // per-slot fp16 exp weights
__device__ __align__(16) int      g_btot  [64];

// ---------------- helpers ----------------------------------------------------
__device__ __forceinline__ float lrelu(float v) { return v > 0.f ? v : NEG * v; }

__device__ __forceinline__ unsigned f2o(float f) {
    unsigned u = __float_as_uint(f);
    return (u & 0x80000000u) ? ~u : (u | 0x80000000u);
}
__device__ __forceinline__ float o2f(unsigned u) {
    return (u & 0x80000000u) ? __uint_as_float(u & 0x7fffffffu)
                             : __uint_as_float(~u);
}

__device__ __forceinline__ void ldm_x4(unsigned& r0, unsigned& r1, unsigned& r2, unsigned& r3,
                                       unsigned addr) {
    asm volatile("ldmatrix.sync.aligned.m8n8.x4.shared.b16 {%0,%1,%2,%3}, [%4];"
                 : "=r"(r0), "=r"(r1), "=r"(r2), "=r"(r3) : "r"(addr));
}
__device__ __forceinline__ void ldm_x4t(unsigned& r0, unsigned& r1, unsigned& r2, unsigned& r3,
                                        unsigned addr) {
    asm volatile("ldmatrix.sync.aligned.m8n8.x4.trans.shared.b16 {%0,%1,%2,%3}, [%4];"
                 : "=r"(r0), "=r"(r1), "=r"(r2), "=r"(r3) : "r"(addr));
}
__device__ __forceinline__ void mma16816(float* c, const unsigned* a, unsigned b0, unsigned b1) {
    asm volatile("mma.sync.aligned.m16n8k16.row.col.f32.f16.f16.f32 "
                 "{%0,%1,%2,%3}, {%4,%5,%6,%7}, {%8,%9}, {%0,%1,%2,%3};"
                 : "+f"(c[0]), "+f"(c[1]), "+f"(c[2]), "+f"(c[3])
                 : "r"(a[0]), "r"(a[1]), "r"(a[2]), "r"(a[3]), "r"(b0), "r"(b1));
}

// ---------------- GEMM1 via HMMA + overlapped degree counting ----------------
// blocks [0,391): GEMM tile (128 nodes).  blocks [391,1173): count+rank x4.
#define XSTR 136   // padded half stride for conflict-free ldmatrix
#define GB1  391
__global__ void __launch_bounds__(256, 2) k_gemm1h(const float* __restrict__ x,
                        const float* __restrict__ W1,
                        const float* __restrict__ a_src, const float* __restrict__ a_dst,
                        const int* __restrict__ ei) {
    const int tid  = threadIdx.x;

    if (blockIdx.x >= GB1) {
        // degree counting + per-edge rank (g_deg pre-zeroed)
        int e0 = ((blockIdx.x - GB1) * 256 + tid) * 4;
        if (e0 < EE) {
            int4 d4 = *(const int4*)(ei + EE + e0);
            int4 r4;
            r4.x = atomicAdd(&g_deg[d4.x], 1);
            r4.y = atomicAdd(&g_deg[d4.y], 1);
            r4.z = atomicAdd(&g_deg[d4.z], 1);
            r4.w = atomicAdd(&g_deg[d4.w], 1);
            *(int4*)(g_rank + e0) = r4;
        }
        return;
    }

    // per-call init of the max cells (consumed by later launches)
    if (blockIdx.x == 0) {
        if (tid < 4)  g_maxu1[tid] = NEGINF_ORD;
        if (tid == 4) g_maxu2[0] = NEGINF_ORD;
    }

    extern __shared__ __half dsm[];
    __half* xs = dsm;                 // [128][XSTR]
    __half* ws = dsm + 128 * XSTR;    // [128][XSTR]

    const int lane = tid & 31;
    const int warp = tid >> 5;
    const int nb   = blockIdx.x * 128;
    const int g    = lane >> 2;
    const int tig  = lane & 3;

    for (int i = tid; i < 128 * 32; i += 256) {
        int r = i >> 5, q = i & 31;
        float4 v = (nb + r < NN) ? *(const float4*)(x + (size_t)(nb + r) * 128 + q * 4)
                                 : make_float4(0.f, 0.f, 0.f, 0.f);
        __half2* dst = (__half2*)(xs + r * XSTR + q * 4);
        dst[0] = __floats2half2_rn(v.x, v.y);
        dst[1] = __floats2half2_rn(v.z, v.w);
    }
    for (int i = tid; i < 128 * 32; i += 256) {
        int r = i >> 5, q = i & 31;
        float4 v = *(const float4*)(W1 + r * 128 + q * 4);
        __half2* dst = (__half2*)(ws + r * XSTR + q * 4);
        dst[0] = __floats2half2_rn(v.x, v.y);
        dst[1] = __floats2half2_rn(v.z, v.w);
    }
    __syncthreads();

    unsigned xs_u = (unsigned)__cvta_generic_to_shared(xs);
    unsigned ws_u = (unsigned)__cvta_generic_to_shared(ws);
    unsigned aaddr = xs_u + ((warp * 16 + (lane & 15)) * XSTR + (lane >> 4) * 8) * 2;
    unsigned baddr = ws_u + ((lane & 15) * XSTR + (lane >> 4) * 8) * 2;

    float c[16][4];
#pragma unroll
    for (int j = 0; j < 16; j++)
#pragma unroll
        for (int q = 0; q < 4; q++) c[j][q] = 0.f;

#pragma unroll
    for (int ks = 0; ks < 8; ks++) {
        unsigned a[4];
        ldm_x4(a[0], a[1], a[2], a[3], aaddr + ks * 32);
#pragma unroll
        for (int p = 0; p < 8; p++) {
            unsigned b0, b1, b2, b3;
            ldm_x4t(b0, b1, b2, b3, baddr + ks * (16 * XSTR * 2) + p * 32);
            mma16816(c[2 * p],     a, b0, b1);
            mma16816(c[2 * p + 1], a, b2, b3);
        }
    }

    int r0 = nb + warp * 16 + g;
    int r1 = r0 + 8;
    bool v0 = r0 < NN, v1 = r1 < NN;
    float ss0[4] = {0, 0, 0, 0}, sd0[4] = {0, 0, 0, 0};
    float ss1[4] = {0, 0, 0, 0}, sd1[4] = {0, 0, 0, 0};
#pragma unroll
    for (int j = 0; j < 16; j++) {
        int col = j * 8 + tig * 2;
        float a0 = a_src[col], a1 = a_src[col + 1];
        float d0 = a_dst[col], d1 = a_dst[col + 1];
        int h = j >> 2;
        ss0[h] += c[j][0] * a0 + c[j][1] * a1;
        sd0[h] += c[j][0] * d0 + c[j][1] * d1;
        ss1[h] += c[j][2] * a0 + c[j][3] * a1;
        sd1[h] += c[j][2] * d0 + c[j][3] * d1;
        if (v0) *(__half2*)(g_h1h + (size_t)r0 * 128 + col) = __floats2half2_rn(c[j][0], c[j][1]);
        if (v1) *(__half2*)(g_h1h + (size_t)r1 * 128 + col) = __floats2half2_rn(c[j][2], c[j][3]);
    }
#pragma unroll
    for (int o = 1; o <= 2; o <<= 1) {
#pragma unroll
        for (int h = 0; h < 4; h++) {
            ss0[h] += __shfl_xor_sync(0xffffffffu, ss0[h], o);
            sd0[h] += __shfl_xor_sync(0xffffffffu, sd0[h], o);
            ss1[h] += __shfl_xor_sync(0xffffffffu, ss1[h], o);
            sd1[h] += __shfl_xor_sync(0xffffffffu, sd1[h], o);
        }
    }
    if (tig == 0) {
        if (v0) {
#pragma unroll
            for (int h = 0; h < 4; h++) {
                g_als1[r0 * 4 + h] = ss0[h];
                g_ald1[r0 * 4 + h] = sd0[h];
            }
        }
        if (v1) {
#pragma unroll
            for (int h = 0; h < 4; h++) {
                g_als1[r1 * 4 + h] = ss1[h];
                g_ald1[r1 * 4 + h] = sd1[h];
            }
        }
    }
}

// ---------------- scanA: per-1024 local scan + als1 max-reduce ---------------
// blocks [0,49): scan (writes g_rowloc).  blocks [49,54): max over als1.
__global__ void k_scanA() {
    if (blockIdx.x >= 49) {
        int t = (blockIdx.x - 49) * 1024 + threadIdx.x;   // 5120 threads
        float m0 = -1e30f, m1 = -1e30f, m2 = -1e30f, m3 = -1e30f;
        for (int n = t; n < NN; n += 5120) {
            float4 a = *(const float4*)(g_als1 + n * 4);
            m0 = fmaxf(m0, a.x); m1 = fmaxf(m1, a.y);
            m2 = fmaxf(m2, a.z); m3 = fmaxf(m3, a.w);
        }
#pragma unroll
        for (int o = 16; o >= 1; o >>= 1) {
            m0 = fmaxf(m0, __shfl_xor_sync(0xffffffffu, m0, o));
            m1 = fmaxf(m1, __shfl_xor_sync(0xffffffffu, m1, o));
            m2 = fmaxf(m2, __shfl_xor_sync(0xffffffffu, m2, o));
            m3 = fmaxf(m3, __shfl_xor_sync(0xffffffffu, m3, o));
        }
        if ((threadIdx.x & 31) == 0) {
            atomicMax(&g_maxu1[0], f2o(m0));
            atomicMax(&g_maxu1[1], f2o(m1));
            atomicMax(&g_maxu1[2], f2o(m2));
            atomicMax(&g_maxu1[3], f2o(m3));
        }
        return;
    }
    __shared__ int sw[32];
    int t = threadIdx.x, b = blockIdx.x;
    int i = b * 1024 + t;
    int v = (i < NN) ? g_deg[i] : 0;
    int x = v;
#pragma unroll
    for (int o = 1; o < 32; o <<= 1) {
        int y = __shfl_up_sync(0xffffffffu, x, o);
        if ((t & 31) >= o) x += y;
    }
    if ((t & 31) == 31) sw[t >> 5] = x;
    __syncthreads();
    if (t < 32) {
        int y = sw[t];
#pragma unroll
        for (int o = 1; o < 32; o <<= 1) {
            int z = __shfl_up_sync(0xffffffffu, y, o);
            if (t >= o) y += z;
        }
        sw[t] = y;
    }
    __syncthreads();
    int off = (t >= 32) ? sw[(t >> 5) - 1] : 0;
    int incl = x + off;
    if (i < NN) g_rowloc[i] = incl - v;     // block-local exclusive
    if (t == 1023) g_btot[b] = incl;
}

// ---------------- fincsr: finalize rowptr + scatter src & fp16 exp weights ---
__global__ void __launch_bounds__(256) k_fincsr(const int* __restrict__ ei) {
    __shared__ int sh_boff[64];
    __shared__ int w0s;
    int t = threadIdx.x;
    int x = 0, v = 0;
    if (t < 64) {
        v = (t < 49) ? g_btot[t] : 0;
        x = v;
#pragma unroll
        for (int o = 1; o < 32; o <<= 1) {
            int y = __shfl_up_sync(0xffffffffu, x, o);
            if ((t & 31) >= o) x += y;
        }
        if (t == 31) w0s = x;
    }
    __syncthreads();
    if (t < 64) sh_boff[t] = (x + ((t >= 32) ? w0s : 0)) - v;
    __syncthreads();

    // finalize rowptr for this block's 64-node slice
    if (t < 64) {
        int i = blockIdx.x * 64 + t;
        if (i < NN) {
            g_rowfin[i] = g_rowloc[i] + sh_boff[i >> 10];
            g_deg[i] = 0;        // restore zeroed state for next call's count
        }
        if (i == NN) g_rowfin[NN] = EE;
    }

    // scatter 4 edges per thread: src id + fp16 exp weights
    int e0 = (blockIdx.x * 256 + t) * 4;
    if (e0 < EE) {
        int4 s4 = *(const int4*)(ei + e0);
        int4 d4 = *(const int4*)(ei + EE + e0);
        int4 r4 = *(const int4*)(g_rank + e0);
        uint4 mu = *(const uint4*)g_maxu1;
        float mx0 = o2f(mu.x), mx1 = o2f(mu.y), mx2 = o2f(mu.z), mx3 = o2f(mu.w);
        int ss[4] = {s4.x, s4.y, s4.z, s4.w};
        int dd[4] = {d4.x, d4.y, d4.z, d4.w};
        int rr[4] = {r4.x, r4.y, r4.z, r4.w};
        float4 as[4], ad[4];
        int p[4];
#pragma unroll
        for (int i = 0; i < 4; i++) {
            as[i] = *(const float4*)(g_als1 + (size_t)ss[i] * 4);
            ad[i] = *(const float4*)(g_ald1 + (size_t)dd[i] * 4);
            p[i]  = __ldg(&g_rowloc[dd[i]]) + sh_boff[dd[i] >> 10] + rr[i];
        }
#pragma unroll
        for (int i = 0; i < 4; i++) {
            float ex = __expf(lrelu(as[i].x + ad[i].x) - lrelu(mx0 + ad[i].x));
            float ey = __expf(lrelu(as[i].y + ad[i].y) - lrelu(mx1 + ad[i].y));
            float ez = __expf(lrelu(as[i].z + ad[i].z) - lrelu(mx2 + ad[i].z));
            float ew = __expf(lrelu(as[i].w + ad[i].w) - lrelu(mx3 + ad[i].w));
            __half2 e01 = __floats2half2_rn(ex, ey);
            __half2 e23 = __floats2half2_rn(ez, ew);
            g_srcl[p[i]] = ss[i];
            __half2* dst = (__half2*)(g_exlh + (size_t)p[i] * 4);
            dst[0] = e01;
            dst[1] = e23;
        }
    }
}

// ---------------- layer-1 aggregation (branchless, 4 edges in flight) --------
// warp per dst node; shfl-broadcast src ids; predicated fp16 weight loads;
// 4 h-row gathers issued before any FMA drains; 2 accumulator chains.
__global__ void __launch_bounds__(256) k_nodeagg1(const float* __restrict__ b1) {
    int gw   = (blockIdx.x * 256 + threadIdx.x) >> 5;   // node id
    int lane = threadIdx.x & 31;
    int sub  = lane >> 4;           // 2 edge slots
    int cl   = lane & 15;           // channel group: channels cl*8..cl*8+7
    int head = cl >> 2;
    bool denlane = (cl & 3) == 0;

    int start = g_rowfin[gw], end = g_rowfin[gw + 1];

    float den_l = 0.f;
    __half2 accA[4], accB[4];
    const __half2 hz = __floats2half2_rn(0.f, 0.f);
#pragma unroll
    for (int j = 0; j < 4; j++) { accA[j] = hz; accB[j] = hz; }

    // self loop (sub 0 only; exp computed here, once per node)
    {
        float ald_h = __ldg(g_ald1 + gw * 4 + head);
        float m_h = lrelu(o2f(g_maxu1[head]) + ald_h);
        float a_h = __ldg(g_als1 + gw * 4 + head);
        float ex = __expf(lrelu(a_h + ald_h) - m_h);
        if (sub == 0 && denlane) den_l = ex;
        if (sub == 0) {
            uint4 u = *(const uint4*)(g_h1h + (size_t)gw * 128 + cl * 8);
            const __half2* hp = (const __half2*)&u;
            __half2 eh = __float2half2_rn(ex);
#pragma unroll
            for (int q = 0; q < 4; q++) accA[q] = __hmul2(eh, hp[q]);
        }
    }

    const __half hzero = __ushort_as_half((unsigned short)0);
    for (int j0 = start; j0 < end; j0 += 32) {
        int idx = j0 + lane;
        int s = (idx < end) ? g_srcl[idx] : 0;
        int cnt = min(32, end - j0);
        for (int t = 0; t < cnt; t += 8) {
            int iA = t + sub, iB = t + 2 + sub, iC = t + 4 + sub, iD = t + 6 + sub;
            int sA = __shfl_sync(0xffffffffu, s, iA & 31);
            int sB = __shfl_sync(0xffffffffu, s, iB & 31);
            int sC = __shfl_sync(0xffffffffu, s, iC & 31);
            int sD = __shfl_sync(0xffffffffu, s, iD & 31);
            __half ehA = (iA < cnt) ? __ldg(g_exlh + (size_t)(j0 + iA) * 4 + head) : hzero;
            __half ehB = (iB < cnt) ? __ldg(g_exlh + (size_t)(j0 + iB) * 4 + head) : hzero;
            __half ehC = (iC < cnt) ? __ldg(g_exlh + (size_t)(j0 + iC) * 4 + head) : hzero;
            __half ehD = (iD < cnt) ? __ldg(g_exlh + (size_t)(j0 + iD) * 4 + head) : hzero;
            uint4 uA = *(const uint4*)(g_h1h + (size_t)sA * 128 + cl * 8);
            uint4 uB = *(const uint4*)(g_h1h + (size_t)sB * 128 + cl * 8);
            uint4 uC = *(const uint4*)(g_h1h + (size_t)sC * 128 + cl * 8);
            uint4 uD = *(const uint4*)(g_h1h + (size_t)sD * 128 + cl * 8);
            den_l += denlane ? (__half2float(ehA) + __half2float(ehB)
                              + __half2float(ehC) + __half2float(ehD)) : 0.f;
            __half2 e2A = __half2half2(ehA);
            __half2 e2B = __half2half2(ehB);
            __half2 e2C = __half2half2(ehC);
            __half2 e2D = __half2half2(ehD);
            const __half2* hA = (const __half2*)&uA;
            const __half2* hB = (const __half2*)&uB;
            const __half2* hC = (const __half2*)&uC;
            const __half2* hD = (const __half2*)&uD;
#pragma unroll
            for (int q = 0; q < 4; q++) {
                accA[q] = __hfma2(e2A, hA[q], accA[q]);
                accB[q] = __hfma2(e2B, hB[q], accB[q]);
            }
#pragma unroll
            for (int q = 0; q < 4; q++) {
                accA[q] = __hfma2(e2C, hC[q], accA[q]);
                accB[q] = __hfma2(e2D, hD[q], accB[q]);
            }
        }
    }

    // to fp32, combine chains + subs
    float accF[8];
#pragma unroll
    for (int q = 0; q < 4; q++) {
        float2 fa = __half22float2(accA[q]);
        float2 fb = __half22float2(accB[q]);
        accF[q * 2]     = fa.x + fb.x;
        accF[q * 2 + 1] = fa.y + fb.y;
    }
#pragma unroll
    for (int j = 0; j < 8; j++) accF[j] += __shfl_xor_sync(0xffffffffu, accF[j], 16);
    den_l += __shfl_xor_sync(0xffffffffu, den_l, 16);
    float den = __shfl_sync(0xffffffffu, den_l, cl & 12, 16);

    // act row (ELU via __expf) -> g_acth fp16
    if (sub == 0) {
        float inv = 1.f / den;
        float4 ba = ((const float4*)b1)[cl * 2];
        float4 bb = ((const float4*)b1)[cl * 2 + 1];
        float r[8];
        r[0] = accF[0] * inv + ba.x;
        r[1] = accF[1] * inv + ba.y;
        r[2] = accF[2] * inv + ba.z;
        r[3] = accF[3] * inv + ba.w;
        r[4] = accF[4] * inv + bb.x;
        r[5] = accF[5] * inv + bb.y;
        r[6] = accF[6] * inv + bb.z;
        r[7] = accF[7] * inv + bb.w;
#pragma unroll
        for (int q = 0; q < 8; q++) r[q] = r[q] > 0.f ? r[q] : (__expf(r[q]) - 1.f);
        uint4 st;
        ((__half2*)&st)[0] = __floats2half2_rn(r[0], r[1]);
        ((__half2*)&st)[1] = __floats2half2_rn(r[2], r[3]);
        ((__half2*)&st)[2] = __floats2half2_rn(r[4], r[5]);
        ((__half2*)&st)[3] = __floats2half2_rn(r[6], r[7]);
        *(uint4*)(g_acth + (size_t)gw * 128 + cl * 8) = st;
    }
}

// ---------------- GEMM2 via HMMA: h2h = fp16(acth @ W2) ; als2/ald2 + max ----
__global__ void __launch_bounds__(256, 2) k_gemm2h(const float* __restrict__ W2,
                        const float* __restrict__ a_src2, const float* __restrict__ a_dst2) {
    extern __shared__ __half dsm2[];
    __half* as_ = dsm2;                // [128][XSTR]
    __half* ws  = dsm2 + 128 * XSTR;   // [128][XSTR], only 16 cols used

    const int tid  = threadIdx.x;
    const int lane = tid & 31;
    const int warp = tid >> 5;
    const int nb   = blockIdx.x * 128;
    const int g    = lane >> 2;
    const int tig  = lane & 3;

    // stage A (acth rows, already fp16)
    for (int i = tid; i < 128 * 16; i += 256) {
        int r = i >> 4, q = i & 15;
        uint4 v = (nb + r < NN) ? *(const uint4*)(g_acth + (size_t)(nb + r) * 128 + q * 8)
                                : make_uint4(0u, 0u, 0u, 0u);
        *(uint4*)(as_ + r * XSTR + q * 8) = v;
    }
    // stage B (W2 128x16 float -> half)
    for (int i = tid; i < 1024; i += 256) {
        int r = i >> 3, q = i & 7;
        float2 v = *(const float2*)(W2 + r * 16 + q * 2);
        *(__half2*)(ws + r * XSTR + q * 2) = __floats2half2_rn(v.x, v.y);
    }
    __syncthreads();

    unsigned as_u = (unsigned)__cvta_generic_to_shared(as_);
    unsigned ws_u = (unsigned)__cvta_generic_to_shared(ws);
    unsigned aaddr = as_u + ((warp * 16 + (lane & 15)) * XSTR + (lane >> 4) * 8) * 2;
    unsigned baddr = ws_u + ((lane & 15) * XSTR + (lane >> 4) * 8) * 2;

    float c[2][4];
#pragma unroll
    for (int j = 0; j < 2; j++)
#pragma unroll
        for (int q = 0; q < 4; q++) c[j][q] = 0.f;

#pragma unroll
    for (int ks = 0; ks < 8; ks++) {
        unsigned a[4];
        ldm_x4(a[0], a[1], a[2], a[3], aaddr + ks * 32);
        unsigned b0, b1, b2, b3;
        ldm_x4t(b0, b1, b2, b3, baddr + ks * (16 * XSTR * 2));
        mma16816(c[0], a, b0, b1);
        mma16816(c[1], a, b2, b3);
    }

    int r0 = nb + warp * 16 + g;
    int r1 = r0 + 8;
    bool v0 = r0 < NN, v1 = r1 < NN;

    float ps0 = 0.f, pd0 = 0.f, ps1 = 0.f, pd1 = 0.f;
#pragma unroll
    for (int j = 0; j < 2; j++) {
        int col = j * 8 + tig * 2;
        float a0 = a_src2[col], a1 = a_src2[col + 1];
        float d0 = a_dst2[col], d1 = a_dst2[col + 1];
        ps0 += c[j][0] * a0 + c[j][1] * a1;
        pd0 += c[j][0] * d0 + c[j][1] * d1;
        ps1 += c[j][2] * a0 + c[j][3] * a1;
        pd1 += c[j][2] * d0 + c[j][3] * d1;
        if (v0) *(__half2*)(g_h2h + (size_t)r0 * 16 + col) = __floats2half2_rn(c[j][0], c[j][1]);
        if (v1) *(__half2*)(g_h2h + (size_t)r1 * 16 + col) = __floats2half2_rn(c[j][2], c[j][3]);
    }
#pragma unroll
    for (int o = 1; o <= 2; o <<= 1) {
        ps0 += __shfl_xor_sync(0xffffffffu, ps0, o);
        pd0 += __shfl_xor_sync(0xffffffffu, pd0, o);
        ps1 += __shfl_xor_sync(0xffffffffu, ps1, o);
        pd1 += __shfl_xor_sync(0xffffffffu, pd1, o);
    }
    float mx = -1e30f;
    if (tig == 0) {
        if (v0) { g_als2[r0] = ps0; g_ald2[r0] = pd0; mx = fmaxf(mx, ps0); }
        if (v1) { g_als2[r1] = ps1; g_ald2[r1] = pd1; mx = fmaxf(mx, ps1); }
    }
#pragma unroll
    for (int o = 16; o >= 1; o >>= 1) mx = fmaxf(mx, __shfl_xor_sync(0xffffffffu, mx, o));
    if (lane == 0) atomicMax(&g_maxu2[0], f2o(mx));
}

// ---------------- layer-2 fused aggregation + log_softmax (branchless) -------
__global__ void __launch_bounds__(256) k_nodeagg2(const float* __restrict__ b2,
                                                  float* __restrict__ out) {
    int gw   = (blockIdx.x * 256 + threadIdx.x) >> 5;
    int lane = threadIdx.x & 31;
    int sub  = lane >> 3, cl = lane & 7;

    float ald = g_ald2[gw];
    float m = lrelu(o2f(g_maxu2[0]) + ald);
    int start = g_rowfin[gw], end = g_rowfin[gw + 1];

    float2 accA = make_float2(0.f, 0.f), accB = make_float2(0.f, 0.f);
    float2 accC = make_float2(0.f, 0.f), accD = make_float2(0.f, 0.f);
    float den_l = 0.f;

    // self loop
    {
        float exs = __expf(lrelu(__ldg(g_als2 + gw) + ald) - m);
        if (lane == 0) den_l = exs;
        if (sub == 0) {
            float2 f = __half22float2(*(const __half2*)(g_h2h + (size_t)gw * 16 + cl * 2));
            accA.x = exs * f.x;
            accA.y = exs * f.y;
        }
    }

    for (int j0 = start; j0 < end; j0 += 32) {
        int idx = j0 + lane;
        int s = (idx < end) ? g_srcl[idx] : 0;
        int cnt = min(32, end - j0);
        for (int t = 0; t < cnt; t += 16) {
            int iA = t + sub, iB = t + 4 + sub, iC = t + 8 + sub, iD = t + 12 + sub;
            int sA = __shfl_sync(0xffffffffu, s, iA & 31);
            int sB = __shfl_sync(0xffffffffu, s, iB & 31);
            int sC = __shfl_sync(0xffffffffu, s, iC & 31);
            int sD = __shfl_sync(0xffffffffu, s, iD & 31);
            float aA = __ldg(g_als2 + sA);
            float aB = __ldg(g_als2 + sB);
            float aC = __ldg(g_als2 + sC);
            float aD = __ldg(g_als2 + sD);
            float2 fA = __half22float2(*(const __half2*)(g_h2h + (size_t)sA * 16 + cl * 2));
            float2 fB = __half22float2(*(const __half2*)(g_h2h + (size_t)sB * 16 + cl * 2));
            float2 fC = __half22float2(*(const __half2*)(g_h2h + (size_t)sC * 16 + cl * 2));
            float2 fD = __half22float2(*(const __half2*)(g_h2h + (size_t)sD * 16 + cl * 2));
            float eA = (iA < cnt) ? __expf(lrelu(aA + ald) - m) : 0.f;
            float eB = (iB < cnt) ? __expf(lrelu(aB + ald) - m) : 0.f;
            float eC = (iC < cnt) ? __expf(lrelu(aC + ald) - m) : 0.f;
            float eD = (iD < cnt) ? __expf(lrelu(aD + ald) - m) : 0.f;
            den_l += (cl == 0) ? (eA + eB + eC + eD) : 0.f;
            accA.x = fmaf(eA, fA.x, accA.x);  accA.y = fmaf(eA, fA.y, accA.y);
            accB.x = fmaf(eB, fB.x, accB.x);  accB.y = fmaf(eB, fB.y, accB.y);
            accC.x = fmaf(eC, fC.x, accC.x);  accC.y = fmaf(eC, fC.y, accC.y);
            accD.x = fmaf(eD, fD.x, accD.x);  accD.y = fmaf(eD, fD.y, accD.y);
        }
    }
    accA.x += accB.x + accC.x + accD.x;
    accA.y += accB.y + accC.y + accD.y;
    accA.x += __shfl_xor_sync(0xffffffffu, accA.x, 8);
    accA.y += __shfl_xor_sync(0xffffffffu, accA.y, 8);
    accA.x += __shfl_xor_sync(0xffffffffu, accA.x, 16);
    accA.y += __shfl_xor_sync(0xffffffffu, accA.y, 16);
    den_l += __shfl_xor_sync(0xffffffffu, den_l, 8);
    den_l += __shfl_xor_sync(0xffffffffu, den_l, 16);
    float den = __shfl_sync(0xffffffffu, den_l, 0);

    float inv = 1.f / den;
    float v0 = accA.x * inv + b2[cl * 2];
    float v1 = accA.y * inv + b2[cl * 2 + 1];
    float mx = fmaxf(v0, v1);
#pragma unroll
    for (int o = 4; o >= 1; o >>= 1) mx = fmaxf(mx, __shfl_xor_sync(0xffffffffu, mx, o, 8));
    float s = __expf(v0 - mx) + __expf(v1 - mx);
#pragma unroll
    for (int o = 4; o >= 1; o >>= 1) s += __shfl_xor_sync(0xffffffffu, s, o, 8);
    if (sub == 0) {
        float ls = __logf(s);
        float2 r = make_float2(v0 - mx - ls, v1 - mx - ls);
        *(float2*)(out + (size_t)gw * 16 + cl * 2) = r;
    }
}

// ---------------- launch ------------------------------------------------------
extern "C" void kernel_launch(void* const* d_in, const int* in_sizes, int n_in,
                              void* d_out, int out_size) {
    const float* x      = (const float*)d_in[0];
    const int*   ei     = (const int*)  d_in[1];
    const float* W1     = (const float*)d_in[2];
    const float* a_src1 = (const float*)d_in[3];
    const float* a_dst1 = (const float*)d_in[4];
    const float* b1     = (const float*)d_in[5];
    const float* W2     = (const float*)d_in[6];
    const float* a_src2 = (const float*)d_in[7];
    const float* a_dst2 = (const float*)d_in[8];
    const float* b2     = (const float*)d_in[9];
    float* out = (float*)d_out;

    const int smem1 = 2 * 128 * XSTR * sizeof(__half);   // 69632
    cudaFuncSetAttribute(k_gemm1h, cudaFuncAttributeMaxDynamicSharedMemorySize, smem1);
    cudaFuncSetAttribute(k_gemm2h, cudaFuncAttributeMaxDynamicSharedMemorySize, smem1);

    k_gemm1h  <<<GB1 + 782, 256, smem1>>>(x, W1, a_src1, a_dst1, ei);
    k_scanA   <<<54, 1024>>>();
    k_fincsr  <<<782, 256>>>(ei);
    k_nodeagg1<<<6250, 256>>>(b1);
    k_gemm2h  <<<391, 256, smem1>>>(W2, a_src2, a_dst2);
    k_nodeagg2<<<6250, 256>>>(b2, out);
}